// round 3
// baseline (speedup 1.0000x reference)
#include <cuda_runtime.h>
#include <math.h>

#define Tt 512
#define Bb 64

// ------------- static device scratch -------------
__device__ float g_xg[2][Tt*Bb*512];      // [dir][(t*64+b)*512+col], reused across layers
__device__ float g_out1[Bb*Tt*256];
__device__ float g_out2[Bb*Tt*256];
__device__ float g_att[Bb*Tt*256];
__device__ float g_S[(size_t)Bb*Tt*Tt];   // gram -> softmaxed weights in place
__device__ float g_h[2][2*Bb*128];        // [layer][dir*B*H + b*H + k]
__device__ float g_hbuf[2][2][Bb*128];    // [phase][dir][b*128+k]
__device__ float g_sc[Tt*Bb];             // attention weights [t][b]
__device__ float g_a2[Bb*256];
__device__ unsigned g_ctr[1024];

__device__ __forceinline__ float sigmf(float x){ return 1.f/(1.f+expf(-x)); }
__device__ __forceinline__ float wsum(float v){
    #pragma unroll
    for (int o=16;o;o>>=1) v += __shfl_xor_sync(0xffffffffu, v, o);
    return v;
}

__global__ void k_init(){ g_ctr[threadIdx.x] = 0u; }

// ------------- layer-1 input projection (embedding fused), both dirs -------------
__global__ __launch_bounds__(256) void k_xg1(
    const int* __restrict__ x, const float* __restrict__ emb,
    const float* __restrict__ Wf, const float* __restrict__ bf1, const float* __restrict__ bf2,
    const float* __restrict__ Wb, const float* __restrict__ bb1, const float* __restrict__ bb2)
{
    __shared__ float wf[5120], wb[5120], bf[512], bb[512], e[10];
    int b = blockIdx.y, t0 = blockIdx.x*64, tid = threadIdx.x;
    for (int i=tid;i<5120;i+=256){ wf[i]=Wf[i]; wb[i]=Wb[i]; }
    for (int i=tid;i<512;i+=256){ bf[i]=bf1[i]+bf2[i]; bb[i]=bb1[i]+bb2[i]; }
    __syncthreads();
    for (int tl=0; tl<64; tl++){
        int t = t0+tl;
        if (tid<10) e[tid] = emb[x[b*Tt+t]*10+tid];
        __syncthreads();
        float ev[10];
        #pragma unroll
        for (int d=0;d<10;d++) ev[d]=e[d];
        for (int c=tid;c<512;c+=256){
            float af=bf[c], ab=bb[c];
            #pragma unroll
            for (int d=0;d<10;d++){ af=fmaf(ev[d],wf[c*10+d],af); ab=fmaf(ev[d],wb[c*10+d],ab); }
            g_xg[0][(t*Bb+b)*512+c]=af;
            g_xg[1][(t*Bb+b)*512+c]=ab;
        }
        __syncthreads();
    }
}

// ------------- persistent bidirectional LSTM recurrence -------------
// 128 CTAs: dir=bid>>6, bslice=(bid&63)>>3 (8 batches), kslice=bid&7 (16 hidden).
__global__ __launch_bounds__(256,1) void k_rec(int layer,
    const float* __restrict__ Whh_f, const float* __restrict__ Whh_b)
{
    __shared__ __align__(16) float wsm[8192];   // float4 idx jb*64+r
    __shared__ __align__(16) float hsh[8][128];
    __shared__ float gsh[8][64];
    int bid = blockIdx.x;
    int dir = bid>>6, rem = bid&63, bsl = rem>>3, ksl = rem&7;
    int k0 = ksl*16;
    const float* Whh = dir? Whh_b : Whh_f;
    const float* xg  = g_xg[dir];
    float* out = layer? g_out2 : g_out1;
    unsigned* ctr = &g_ctr[(layer*16 + dir*8 + bsl)*32];
    int tid = threadIdx.x;

    for (int idx=tid; idx<8192; idx+=256){
        int r = idx>>7, j = idx&127;
        int gate = r>>4, kl = r&15;
        wsm[(j>>2)*256 + r*4 + (j&3)] = Whh[(gate*128 + k0 + kl)*128 + j];
    }
    for (int idx=tid; idx<1024; idx+=256) ((float*)hsh)[idx] = 0.f;

    int r = tid&63, bp = tid>>6;                 // gate thread: row r, batch pair bp
    int gcol = (r>>4)*128 + k0 + (r&15);
    int bg0 = bsl*8 + bp*2, bg1 = bg0+1;
    int cbl = tid>>4, ckl = tid&15;              // cell thread (tid<128)
    int cb  = bsl*8 + cbl;
    float cst = 0.f;
    __syncthreads();

    const float4* w4 = (const float4*)wsm;
    int tI = dir? 511 : 0;
    float xgc0 = __ldg(&xg[(tI*Bb+bg0)*512+gcol]);
    float xgc1 = __ldg(&xg[(tI*Bb+bg1)*512+gcol]);

    for (int s=0; s<Tt; s++){
        int t = dir ? (511-s) : s;
        float a0=0.f, a1=0.f;
        const float4* h0 = (const float4*)hsh[bp*2];
        const float4* h1 = (const float4*)hsh[bp*2+1];
        #pragma unroll
        for (int jb=0;jb<32;jb++){
            float4 w = w4[jb*64 + r];
            float4 ha = h0[jb], hb = h1[jb];
            a0=fmaf(w.x,ha.x,a0); a0=fmaf(w.y,ha.y,a0); a0=fmaf(w.z,ha.z,a0); a0=fmaf(w.w,ha.w,a0);
            a1=fmaf(w.x,hb.x,a1); a1=fmaf(w.y,hb.y,a1); a1=fmaf(w.z,hb.z,a1); a1=fmaf(w.w,hb.w,a1);
        }
        gsh[bp*2][r]   = a0 + xgc0;
        gsh[bp*2+1][r] = a1 + xgc1;
        if (s<511){
            int tn = dir? (510-s) : (s+1);
            xgc0 = __ldg(&xg[(tn*Bb+bg0)*512+gcol]);
            xgc1 = __ldg(&xg[(tn*Bb+bg1)*512+gcol]);
        }
        __syncthreads();
        if (tid<128){
            float gi=gsh[cbl][ckl], gf=gsh[cbl][16+ckl], gg=gsh[cbl][32+ckl], go=gsh[cbl][48+ckl];
            cst = sigmf(gf)*cst + sigmf(gi)*tanhf(gg);
            float hv = sigmf(go)*tanhf(cst);
            g_hbuf[s&1][dir][cb*128 + k0 + ckl] = hv;
            out[(cb*Tt + t)*256 + dir*128 + k0 + ckl] = hv;
            if (s==511) g_h[layer][dir*Bb*128 + cb*128 + k0 + ckl] = hv;
            __threadfence();
        }
        __syncthreads();
        if (tid==0){
            atomicAdd(ctr, 1u);
            unsigned tgt = 8u*(unsigned)(s+1);
            while (*((volatile unsigned*)ctr) < tgt) __nanosleep(32);
        }
        __syncthreads();
        if (s<511){
            const float* hb_ = &g_hbuf[s&1][dir][bsl*1024];
            for (int idx=tid; idx<1024; idx+=256) ((float*)hsh)[idx] = __ldcg(&hb_[idx]);
        }
        __syncthreads();
    }
}

// ------------- prefix gram S[b][i][t]=dot/max(i,1), lower-tri tiles -------------
__global__ __launch_bounds__(256) void k_gram(){
    int ti=blockIdx.x, tj=blockIdx.y, b=blockIdx.z;
    if (tj>ti) return;
    __shared__ float As[32][33], Bs[32][33];
    int tid=threadIdx.x;
    const float* O = g_out1 + (size_t)b*Tt*256;
    int i0=ti*32, t0=tj*32;
    int il=tid>>3, tq=tid&7;
    float acc[4]={0,0,0,0};
    for (int kc=0;kc<256;kc+=32){
        int rr=tid>>5, cc=tid&31;
        #pragma unroll
        for (int p=0;p<4;p++){
            As[rr+p*8][cc]=O[(i0+rr+p*8)*256+kc+cc];
            Bs[rr+p*8][cc]=O[(t0+rr+p*8)*256+kc+cc];
        }
        __syncthreads();
        #pragma unroll
        for (int kk=0;kk<32;kk++){
            float a=As[il][kk];
            #pragma unroll
            for (int q=0;q<4;q++) acc[q]=fmaf(a,Bs[tq*4+q][kk],acc[q]);
        }
        __syncthreads();
    }
    int i=i0+il;
    float sc=1.f/(float)(i>0?i:1);
    float* Srow=&g_S[((size_t)b*Tt+i)*Tt + t0];
    #pragma unroll
    for (int q=0;q<4;q++) Srow[tq*4+q]=acc[q]*sc;
}

// ------------- softmax over batch per (i,t), t<i -------------
__global__ void k_bsoft(){
    int i=blockIdx.x, t=threadIdx.x;
    if (t>=i) return;
    size_t base=(size_t)i*Tt+t;
    float v[64], m=-1e30f;
    #pragma unroll
    for (int b=0;b<64;b++){ v[b]=g_S[(size_t)b*Tt*Tt+base]; m=fmaxf(m,v[b]); }
    float s=0.f;
    #pragma unroll
    for (int b=0;b<64;b++){ v[b]=expf(v[b]-m); s+=v[b]; }
    float inv=1.f/s;
    #pragma unroll
    for (int b=0;b<64;b++) g_S[(size_t)b*Tt*Tt+base]=v[b]*inv;
}

// ------------- att[b][i][:] = sum_{t<i} W[b,i,t]*out1[b,t,:] -------------
__global__ __launch_bounds__(256) void k_apply(){
    int i0=blockIdx.x*32, d0=blockIdx.y*64, b=blockIdx.z;
    __shared__ float Ws[32][33], Os[32][65];
    int tid=threadIdx.x;
    int tx=tid&15, ty=tid>>4;
    float acc[2][4]={};
    const float* O=g_out1+(size_t)b*Tt*256;
    const float* W=g_S+(size_t)b*Tt*Tt;
    int kmax=i0+32;
    for (int t0=0;t0<kmax;t0+=32){
        int rr=tid>>5, cc=tid&31;
        #pragma unroll
        for (int p=0;p<4;p++){
            int ii=rr+p*8;
            Ws[ii][cc] = (t0+cc < i0+ii) ? W[(size_t)(i0+ii)*Tt + t0+cc] : 0.f;
        }
        for (int e=tid;e<2048;e+=256) Os[e>>6][e&63]=O[(t0+(e>>6))*256+d0+(e&63)];
        __syncthreads();
        #pragma unroll
        for (int kk=0;kk<32;kk++){
            float w0=Ws[ty][kk], w1=Ws[ty+16][kk];
            #pragma unroll
            for (int q=0;q<4;q++){
                float o=Os[kk][tx*4+q];
                acc[0][q]=fmaf(w0,o,acc[0][q]);
                acc[1][q]=fmaf(w1,o,acc[1][q]);
            }
        }
        __syncthreads();
    }
    float* A=g_att+(size_t)b*Tt*256;
    #pragma unroll
    for (int h=0;h<2;h++){
        int i=i0+ty+h*16;
        #pragma unroll
        for (int q=0;q<4;q++) A[i*256+d0+tx*4+q]=acc[h][q];
    }
}

// ------------- full attention: scores + softmax over batch (per t) -------------
__global__ void k_score(int layer){
    const float* O = layer? g_out2 : g_out1;
    const float* h = g_h[layer];
    int t=blockIdx.x, tid=threadIdx.x, w=tid>>5, lane=tid&31;
    __shared__ float sc[64];
    for (int j=0;j<8;j++){
        int b=w*8+j;
        const float* o=O+((size_t)b*Tt+t)*256;
        const float* hb=h+b*256;
        float a=0.f;
        for (int k=lane;k<256;k+=32) a=fmaf(o[k],hb[k],a);
        a=wsum(a);
        if (lane==0) sc[b]=a*(1.f/512.f);
    }
    __syncthreads();
    if (tid<32){
        float v0=sc[tid], v1=sc[tid+32];
        float m=fmaxf(v0,v1);
        #pragma unroll
        for (int o=16;o;o>>=1) m=fmaxf(m,__shfl_xor_sync(0xffffffffu,m,o));
        float e0=expf(v0-m), e1=expf(v1-m);
        float s=e0+e1;
        s=wsum(s);
        float inv=1.f/s;
        g_sc[t*64+tid]=e0*inv;
        g_sc[t*64+tid+32]=e1*inv;
    }
}

__global__ void k_fsum(int layer){
    const float* O = layer? g_out2 : g_out1;
    int b=blockIdx.x, d=threadIdx.x;
    float a=0.f;
    const float* o=O+(size_t)b*Tt*256;
    for (int t=0;t<Tt;t++) a=fmaf(g_sc[t*64+b], o[t*256+d], a);
    if (layer==0) g_att[((size_t)b*Tt+511)*256+d]=a;
    else          g_a2[b*256+d]=a;
}

// ------------- layer-2 input projection GEMM: xg2 = att @ Wih2^T + bias -------------
__global__ __launch_bounds__(256) void k_xg2(
    const float* __restrict__ Wf, const float* __restrict__ bf1, const float* __restrict__ bf2,
    const float* __restrict__ Wb, const float* __restrict__ bb1, const float* __restrict__ bb2)
{
    int mt=blockIdx.x, col0=blockIdx.y*64, dir=blockIdx.z;
    const float* W2 = dir? Wb : Wf;
    __shared__ float As[64][17], Bs[16][65], bsh[64];
    int tid=threadIdx.x;
    if (tid<64) bsh[tid] = dir? (bb1[col0+tid]+bb2[col0+tid]) : (bf1[col0+tid]+bf2[col0+tid]);
    int tx=tid&15, ty=tid>>4;
    float acc[4][4]={};
    for (int kc=0;kc<256;kc+=16){
        for (int e=tid;e<1024;e+=256){
            int rr=e>>4, kk=e&15;
            As[rr][kk]=g_att[((size_t)rr*Tt+mt)*256 + kc+kk];
        }
        {
            int e=tid; int cc=e>>2, k4=(e&3)*4;
            const float4 w = *(const float4*)&W2[(col0+cc)*256 + kc+k4];
            Bs[k4][cc]=w.x; Bs[k4+1][cc]=w.y; Bs[k4+2][cc]=w.z; Bs[k4+3][cc]=w.w;
        }
        __syncthreads();
        #pragma unroll
        for (int kk=0;kk<16;kk++){
            float av[4], bv[4];
            #pragma unroll
            for (int q=0;q<4;q++){ av[q]=As[ty*4+q][kk]; bv[q]=Bs[kk][tx*4+q]; }
            #pragma unroll
            for (int q=0;q<4;q++)
                #pragma unroll
                for (int j=0;j<4;j++) acc[q][j]=fmaf(av[q],bv[j],acc[q][j]);
        }
        __syncthreads();
    }
    #pragma unroll
    for (int q=0;q<4;q++){
        int b=ty*4+q;
        #pragma unroll
        for (int j=0;j<4;j++){
            int c=col0+tx*4+j;
            g_xg[dir][(mt*64+b)*512 + c] = acc[q][j] + bsh[tx*4+j];
        }
    }
}

__global__ void k_final(const float* __restrict__ W, const float* __restrict__ bb, float* out){
    __shared__ float w[256];
    int tid=threadIdx.x;
    for (int i=tid;i<256;i+=64) w[i]=W[i];
    __syncthreads();
    float a=bb[0];
    for (int k=0;k<256;k++) a=fmaf(g_a2[tid*256+k],w[k],a);
    out[tid]=1.f/(1.f+expf(-a));
}

extern "C" void kernel_launch(void* const* d_in, const int* in_sizes, int n_in,
                              void* d_out, int out_size)
{
    const int*   x   = (const int*)  d_in[0];
    const float* emb = (const float*)d_in[1];
    const float* l1Wihf=(const float*)d_in[2],  *l1Whhf=(const float*)d_in[3];
    const float* l1bihf=(const float*)d_in[4],  *l1bhhf=(const float*)d_in[5];
    const float* l1Wihb=(const float*)d_in[6],  *l1Whhb=(const float*)d_in[7];
    const float* l1bihb=(const float*)d_in[8],  *l1bhhb=(const float*)d_in[9];
    const float* l2Wihf=(const float*)d_in[10], *l2Whhf=(const float*)d_in[11];
    const float* l2bihf=(const float*)d_in[12], *l2bhhf=(const float*)d_in[13];
    const float* l2Wihb=(const float*)d_in[14], *l2Whhb=(const float*)d_in[15];
    const float* l2bihb=(const float*)d_in[16], *l2bhhb=(const float*)d_in[17];
    const float* linW=(const float*)d_in[18],   *linb=(const float*)d_in[19];
    float* out=(float*)d_out;

    k_init<<<1,1024>>>();
    k_xg1<<<dim3(8,64),256>>>(x,emb,l1Wihf,l1bihf,l1bhhf,l1Wihb,l1bihb,l1bhhb);
    k_rec<<<128,256>>>(0,l1Whhf,l1Whhb);
    k_gram<<<dim3(16,16,64),256>>>();
    k_bsoft<<<512,512>>>();
    k_apply<<<dim3(16,4,64),256>>>();
    k_score<<<512,256>>>(0);
    k_fsum<<<64,256>>>(0);
    k_xg2<<<dim3(512,8,2),256>>>(l2Wihf,l2bihf,l2bhhf,l2Wihb,l2bihb,l2bhhb);
    k_rec<<<128,256>>>(1,l2Whhf,l2Whhb);
    k_score<<<512,256>>>(1);
    k_fsum<<<64,256>>>(1);
    k_final<<<1,64>>>(linW,linb,out);
}

// round 4
// speedup vs baseline: 1.1712x; 1.1712x over previous
#include <cuda_runtime.h>
#include <math.h>

#define Tt 512
#define Bb 64

// ------------- static device scratch -------------
__device__ float g_xg[2][Tt*Bb*512];      // [dir][(t*64+b)*512+col], reused across layers
__device__ float g_out1[Bb*Tt*256];
__device__ float g_out2[Bb*Tt*256];
__device__ float g_att[Bb*Tt*256];
__device__ float g_S[(size_t)Bb*Tt*Tt];   // gram -> softmaxed weights in place
__device__ float g_h[2][2*Bb*128];        // [layer][dir*B*H + b*H + k]
__device__ float g_hbuf[2][2][Bb*128];    // [phase][dir][b*128+k]
__device__ float g_sc[Tt*Bb];             // attention weights [t][b]
__device__ float g_a2[Bb*256];
__device__ unsigned g_ctr[1024];

__device__ __forceinline__ float sigmf(float x){ return 1.f/(1.f+expf(-x)); }
__device__ __forceinline__ float wsum(float v){
    #pragma unroll
    for (int o=16;o;o>>=1) v += __shfl_xor_sync(0xffffffffu, v, o);
    return v;
}
__device__ __forceinline__ void fma2(unsigned long long &acc, unsigned long long a, unsigned long long b){
    asm("fma.rn.f32x2 %0, %1, %2, %0;" : "+l"(acc) : "l"(a), "l"(b));
}

__global__ void k_init(){ g_ctr[threadIdx.x] = 0u; }

// ------------- layer-1 input projection (embedding fused), both dirs -------------
__global__ __launch_bounds__(256) void k_xg1(
    const int* __restrict__ x, const float* __restrict__ emb,
    const float* __restrict__ Wf, const float* __restrict__ bf1, const float* __restrict__ bf2,
    const float* __restrict__ Wb, const float* __restrict__ bb1, const float* __restrict__ bb2)
{
    __shared__ float wf[5120], wb[5120], bf[512], bb[512], e[10];
    int b = blockIdx.y, t0 = blockIdx.x*64, tid = threadIdx.x;
    for (int i=tid;i<5120;i+=256){ wf[i]=Wf[i]; wb[i]=Wb[i]; }
    for (int i=tid;i<512;i+=256){ bf[i]=bf1[i]+bf2[i]; bb[i]=bb1[i]+bb2[i]; }
    __syncthreads();
    for (int tl=0; tl<64; tl++){
        int t = t0+tl;
        if (tid<10) e[tid] = emb[x[b*Tt+t]*10+tid];
        __syncthreads();
        float ev[10];
        #pragma unroll
        for (int d=0;d<10;d++) ev[d]=e[d];
        for (int c=tid;c<512;c+=256){
            float af=bf[c], ab=bb[c];
            #pragma unroll
            for (int d=0;d<10;d++){ af=fmaf(ev[d],wf[c*10+d],af); ab=fmaf(ev[d],wb[c*10+d],ab); }
            g_xg[0][(t*Bb+b)*512+c]=af;
            g_xg[1][(t*Bb+b)*512+c]=ab;
        }
        __syncthreads();
    }
}

// ------------- persistent bidirectional LSTM recurrence -------------
// 128 CTAs: dir=bid>>6, bslice=(bid&63)>>3 (8 batches), kslice=bid&7 (16 hidden).
// Whh rows held in registers as packed f32x2 pairs; h broadcast from smem;
// gates via fma.rn.f32x2; single-thread release/acquire global barrier per step.
__global__ __launch_bounds__(256,1) void k_rec(int layer,
    const float* __restrict__ Whh_f, const float* __restrict__ Whh_b)
{
    __shared__ __align__(16) float hsh[8][128];
    __shared__ float gsh[8][64];
    int bid = blockIdx.x;
    int dir = bid>>6, rem = bid&63, bsl = rem>>3, ksl = rem&7;
    int k0 = ksl*16;
    const float* Whh = dir? Whh_b : Whh_f;
    const float* xg  = g_xg[dir];
    float* out = layer? g_out2 : g_out1;
    unsigned* ctr = &g_ctr[(layer*16 + dir*8 + bsl)*32];
    int tid = threadIdx.x;

    int r = tid&63, bp = tid>>6;                 // gate col r, batch pair bp
    int grow = (r>>4)*128 + k0 + (r&15);         // Whh row == xg column
    // load this gate column's 128 weights into 64 packed f32x2 register pairs
    unsigned long long wp[64];
    {
        const float4* wr = (const float4*)&Whh[grow*128];
        #pragma unroll
        for (int i=0;i<32;i++){
            float4 w = __ldg(&wr[i]);
            asm("mov.b64 %0, {%1,%2};" : "=l"(wp[2*i])   : "f"(w.x), "f"(w.y));
            asm("mov.b64 %0, {%1,%2};" : "=l"(wp[2*i+1]) : "f"(w.z), "f"(w.w));
        }
    }
    for (int idx=tid; idx<1024; idx+=256) ((float*)hsh)[idx] = 0.f;

    int bg0 = bsl*8 + bp*2, bg1 = bg0+1;
    int cbl = tid>>4, ckl = tid&15;              // cell thread (tid<128)
    int cb  = bsl*8 + cbl;
    float cst = 0.f;
    __syncthreads();

    const unsigned long long* h0p = (const unsigned long long*)&hsh[bp*2][0];
    const unsigned long long* h1p = (const unsigned long long*)&hsh[bp*2+1][0];

    int tI = dir? 511 : 0;
    float xgc0 = __ldg(&xg[(tI*Bb+bg0)*512+grow]);
    float xgc1 = __ldg(&xg[(tI*Bb+bg1)*512+grow]);

    for (int s=0; s<Tt; s++){
        int t = dir ? (511-s) : s;
        unsigned long long a0e=0ull, a0o=0ull, a1e=0ull, a1o=0ull;
        #pragma unroll
        for (int i=0;i<32;i++){
            unsigned long long he0=h0p[2*i], ho0=h0p[2*i+1];
            unsigned long long he1=h1p[2*i], ho1=h1p[2*i+1];
            fma2(a0e, wp[2*i],   he0);
            fma2(a1e, wp[2*i],   he1);
            fma2(a0o, wp[2*i+1], ho0);
            fma2(a1o, wp[2*i+1], ho1);
        }
        float l0,h0,l1,h1,l2,h2,l3,h3;
        asm("mov.b64 {%0,%1}, %2;" : "=f"(l0),"=f"(h0) : "l"(a0e));
        asm("mov.b64 {%0,%1}, %2;" : "=f"(l1),"=f"(h1) : "l"(a0o));
        asm("mov.b64 {%0,%1}, %2;" : "=f"(l2),"=f"(h2) : "l"(a1e));
        asm("mov.b64 {%0,%1}, %2;" : "=f"(l3),"=f"(h3) : "l"(a1o));
        gsh[bp*2][r]   = (l0+h0) + (l1+h1) + xgc0;
        gsh[bp*2+1][r] = (l2+h2) + (l3+h3) + xgc1;
        if (s<511){
            int tn = dir? (510-s) : (s+1);
            xgc0 = __ldg(&xg[(tn*Bb+bg0)*512+grow]);
            xgc1 = __ldg(&xg[(tn*Bb+bg1)*512+grow]);
        }
        __syncthreads();
        if (tid<128){
            float gi=gsh[cbl][ckl], gf=gsh[cbl][16+ckl], gg=gsh[cbl][32+ckl], go=gsh[cbl][48+ckl];
            cst = sigmf(gf)*cst + sigmf(gi)*tanhf(gg);
            float hv = sigmf(go)*tanhf(cst);
            g_hbuf[s&1][dir][cb*128 + k0 + ckl] = hv;
            out[(cb*Tt + t)*256 + dir*128 + k0 + ckl] = hv;
            if (s==511) g_h[layer][dir*Bb*128 + cb*128 + k0 + ckl] = hv;
        }
        __syncthreads();
        if (tid==0){
            asm volatile("fence.acq_rel.gpu;" ::: "memory");
            atomicAdd(ctr, 1u);
            unsigned tgt = 8u*(unsigned)(s+1), v;
            do {
                asm volatile("ld.acquire.gpu.b32 %0, [%1];" : "=r"(v) : "l"(ctr) : "memory");
            } while (v < tgt);
        }
        __syncthreads();
        if (s<511){
            const float* hb_ = &g_hbuf[s&1][dir][bsl*1024];
            for (int idx=tid; idx<1024; idx+=256) ((float*)hsh)[idx] = __ldcg(&hb_[idx]);
        }
        __syncthreads();
    }
}

// ------------- prefix gram S[b][i][t]=dot/max(i,1), 64x64 lower-tri tiles -------------
__global__ __launch_bounds__(256) void k_gram(){
    int ti=blockIdx.x, tj=blockIdx.y, b=blockIdx.z;
    if (tj>ti) return;
    __shared__ float As[64][17], Bs[64][17];
    const float* O = g_out1 + (size_t)b*Tt*256;
    int i0=ti*64, t0=tj*64, tid=threadIdx.x;
    int ty=tid>>4, tx=tid&15;
    float acc[4][4]={};
    for (int kc=0;kc<256;kc+=16){
        #pragma unroll
        for (int p=0;p<4;p++){
            int e=tid+p*256; int rr=e>>4, kk=e&15;
            As[rr][kk]=O[(i0+rr)*256+kc+kk];
            Bs[rr][kk]=O[(t0+rr)*256+kc+kk];
        }
        __syncthreads();
        #pragma unroll
        for (int kk=0;kk<16;kk++){
            float av[4],bv[4];
            #pragma unroll
            for (int q=0;q<4;q++){ av[q]=As[ty*4+q][kk]; bv[q]=Bs[tx*4+q][kk]; }
            #pragma unroll
            for (int q=0;q<4;q++)
                #pragma unroll
                for (int j=0;j<4;j++) acc[q][j]=fmaf(av[q],bv[j],acc[q][j]);
        }
        __syncthreads();
    }
    #pragma unroll
    for (int q=0;q<4;q++){
        int i=i0+ty*4+q;
        float sc=1.f/(float)(i>0?i:1);
        float* Sr=&g_S[((size_t)b*Tt+i)*Tt+t0];
        #pragma unroll
        for (int j=0;j<4;j++) Sr[tx*4+j]=acc[q][j]*sc;
    }
}

// ------------- softmax over batch per (i,t), t<i -------------
__global__ void k_bsoft(){
    int i=blockIdx.x, t=threadIdx.x;
    if (t>=i) return;
    size_t base=(size_t)i*Tt+t;
    float v[64], m=-1e30f;
    #pragma unroll
    for (int b=0;b<64;b++){ v[b]=g_S[(size_t)b*Tt*Tt+base]; m=fmaxf(m,v[b]); }
    float s=0.f;
    #pragma unroll
    for (int b=0;b<64;b++){ v[b]=expf(v[b]-m); s+=v[b]; }
    float inv=1.f/s;
    #pragma unroll
    for (int b=0;b<64;b++) g_S[(size_t)b*Tt*Tt+base]=v[b]*inv;
}

// ------------- att[b][i][:] = sum_{t<i} W[b,i,t]*out1[b,t,:], 64x64 tiles -------------
__global__ __launch_bounds__(256) void k_apply(){
    int i0=blockIdx.x*64, d0=blockIdx.y*64, b=blockIdx.z;
    __shared__ float Ws[64][17], Os[16][65];
    const float* O=g_out1+(size_t)b*Tt*256;
    const float* W=g_S+(size_t)b*Tt*Tt;
    int tid=threadIdx.x, ty=tid>>4, tx=tid&15;
    float acc[4][4]={};
    int kmax=i0+64;
    for (int tk=0;tk<kmax;tk+=16){
        #pragma unroll
        for (int p=0;p<4;p++){
            int e=tid+p*256; int rr=e>>4, kk=e&15;
            int tg=tk+kk;
            Ws[rr][kk] = (tg < i0+rr) ? W[(size_t)(i0+rr)*Tt+tg] : 0.f;
        }
        #pragma unroll
        for (int p=0;p<4;p++){
            int e=tid+p*256; int kk=e>>6, cc=e&63;
            Os[kk][cc]=O[(tk+kk)*256+d0+cc];
        }
        __syncthreads();
        #pragma unroll
        for (int kk=0;kk<16;kk++){
            float wv[4],ov[4];
            #pragma unroll
            for (int q=0;q<4;q++){ wv[q]=Ws[ty*4+q][kk]; ov[q]=Os[kk][tx*4+q]; }
            #pragma unroll
            for (int q=0;q<4;q++)
                #pragma unroll
                for (int j=0;j<4;j++) acc[q][j]=fmaf(wv[q],ov[j],acc[q][j]);
        }
        __syncthreads();
    }
    float* A=g_att+(size_t)b*Tt*256;
    #pragma unroll
    for (int q=0;q<4;q++){
        int i=i0+ty*4+q;
        #pragma unroll
        for (int j=0;j<4;j++) A[i*256+d0+tx*4+j]=acc[q][j];
    }
}

// ------------- full attention: scores + softmax over batch (per t) -------------
__global__ void k_score(int layer){
    const float* O = layer? g_out2 : g_out1;
    const float* h = g_h[layer];
    int t=blockIdx.x, tid=threadIdx.x, w=tid>>5, lane=tid&31;
    __shared__ float sc[64];
    for (int j=0;j<8;j++){
        int b=w*8+j;
        const float* o=O+((size_t)b*Tt+t)*256;
        const float* hb=h+b*256;
        float a=0.f;
        for (int k=lane;k<256;k+=32) a=fmaf(o[k],hb[k],a);
        a=wsum(a);
        if (lane==0) sc[b]=a*(1.f/512.f);
    }
    __syncthreads();
    if (tid<32){
        float v0=sc[tid], v1=sc[tid+32];
        float m=fmaxf(v0,v1);
        #pragma unroll
        for (int o=16;o;o>>=1) m=fmaxf(m,__shfl_xor_sync(0xffffffffu,m,o));
        float e0=expf(v0-m), e1=expf(v1-m);
        float s=e0+e1;
        s=wsum(s);
        float inv=1.f/s;
        g_sc[t*64+tid]=e0*inv;
        g_sc[t*64+tid+32]=e1*inv;
    }
}

__global__ void k_fsum(int layer){
    const float* O = layer? g_out2 : g_out1;
    int b=blockIdx.x, d=threadIdx.x;
    float a=0.f;
    const float* o=O+(size_t)b*Tt*256;
    for (int t=0;t<Tt;t++) a=fmaf(g_sc[t*64+b], o[t*256+d], a);
    if (layer==0) g_att[((size_t)b*Tt+511)*256+d]=a;
    else          g_a2[b*256+d]=a;
}

// ------------- layer-2 input projection GEMM: xg2 = att @ Wih2^T + bias -------------
__global__ __launch_bounds__(256) void k_xg2(
    const float* __restrict__ Wf, const float* __restrict__ bf1, const float* __restrict__ bf2,
    const float* __restrict__ Wb, const float* __restrict__ bb1, const float* __restrict__ bb2)
{
    int mt=blockIdx.x, col0=blockIdx.y*64, dir=blockIdx.z;
    const float* W2 = dir? Wb : Wf;
    __shared__ float As[64][17], Bs[16][65], bsh[64];
    int tid=threadIdx.x;
    if (tid<64) bsh[tid] = dir? (bb1[col0+tid]+bb2[col0+tid]) : (bf1[col0+tid]+bf2[col0+tid]);
    int tx=tid&15, ty=tid>>4;
    float acc[4][4]={};
    for (int kc=0;kc<256;kc+=16){
        for (int e=tid;e<1024;e+=256){
            int rr=e>>4, kk=e&15;
            As[rr][kk]=g_att[((size_t)rr*Tt+mt)*256 + kc+kk];
        }
        {
            int e=tid; int cc=e>>2, k4=(e&3)*4;
            const float4 w = *(const float4*)&W2[(col0+cc)*256 + kc+k4];
            Bs[k4][cc]=w.x; Bs[k4+1][cc]=w.y; Bs[k4+2][cc]=w.z; Bs[k4+3][cc]=w.w;
        }
        __syncthreads();
        #pragma unroll
        for (int kk=0;kk<16;kk++){
            float av[4], bv[4];
            #pragma unroll
            for (int q=0;q<4;q++){ av[q]=As[ty*4+q][kk]; bv[q]=Bs[kk][tx*4+q]; }
            #pragma unroll
            for (int q=0;q<4;q++)
                #pragma unroll
                for (int j=0;j<4;j++) acc[q][j]=fmaf(av[q],bv[j],acc[q][j]);
        }
        __syncthreads();
    }
    #pragma unroll
    for (int q=0;q<4;q++){
        int b=ty*4+q;
        #pragma unroll
        for (int j=0;j<4;j++){
            int c=col0+tx*4+j;
            g_xg[dir][(mt*64+b)*512 + c] = acc[q][j] + bsh[tx*4+j];
        }
    }
}

__global__ void k_final(const float* __restrict__ W, const float* __restrict__ bb, float* out){
    __shared__ float w[256];
    int tid=threadIdx.x;
    for (int i=tid;i<256;i+=64) w[i]=W[i];
    __syncthreads();
    float a=bb[0];
    for (int k=0;k<256;k++) a=fmaf(g_a2[tid*256+k],w[k],a);
    out[tid]=1.f/(1.f+expf(-a));
}

extern "C" void kernel_launch(void* const* d_in, const int* in_sizes, int n_in,
                              void* d_out, int out_size)
{
    const int*   x   = (const int*)  d_in[0];
    const float* emb = (const float*)d_in[1];
    const float* l1Wihf=(const float*)d_in[2],  *l1Whhf=(const float*)d_in[3];
    const float* l1bihf=(const float*)d_in[4],  *l1bhhf=(const float*)d_in[5];
    const float* l1Wihb=(const float*)d_in[6],  *l1Whhb=(const float*)d_in[7];
    const float* l1bihb=(const float*)d_in[8],  *l1bhhb=(const float*)d_in[9];
    const float* l2Wihf=(const float*)d_in[10], *l2Whhf=(const float*)d_in[11];
    const float* l2bihf=(const float*)d_in[12], *l2bhhf=(const float*)d_in[13];
    const float* l2Wihb=(const float*)d_in[14], *l2Whhb=(const float*)d_in[15];
    const float* l2bihb=(const float*)d_in[16], *l2bhhb=(const float*)d_in[17];
    const float* linW=(const float*)d_in[18],   *linb=(const float*)d_in[19];
    float* out=(float*)d_out;

    k_init<<<1,1024>>>();
    k_xg1<<<dim3(8,64),256>>>(x,emb,l1Wihf,l1bihf,l1bhhf,l1Wihb,l1bihb,l1bhhb);
    k_rec<<<128,256>>>(0,l1Whhf,l1Whhb);
    k_gram<<<dim3(8,8,64),256>>>();
    k_bsoft<<<512,512>>>();
    k_apply<<<dim3(8,4,64),256>>>();
    k_score<<<512,256>>>(0);
    k_fsum<<<64,256>>>(0);
    k_xg2<<<dim3(512,8,2),256>>>(l2Wihf,l2bihf,l2bhhf,l2Wihb,l2bihb,l2bhhb);
    k_rec<<<128,256>>>(1,l2Whhf,l2Whhb);
    k_score<<<512,256>>>(1);
    k_fsum<<<64,256>>>(1);
    k_final<<<1,64>>>(linW,linb,out);
}

// round 6
// speedup vs baseline: 1.8919x; 1.6153x over previous
#include <cuda_runtime.h>
#include <stdint.h>
#include <math.h>

#define Tt 512
#define Bb 64

// ------------- static device scratch -------------
__device__ float g_xg[2][Tt*Bb*512];      // [dir][(t*64+b)*512+col], reused across layers
__device__ float g_out1[Bb*Tt*256];
__device__ float g_out2[Bb*Tt*256];
__device__ float g_att[Bb*Tt*256];
__device__ float g_S[(size_t)Bb*Tt*Tt];   // gram -> softmaxed weights in place
__device__ float g_h[2][2*Bb*128];        // [layer][dir*B*H + b*H + k]
__device__ float g_sc[Tt*Bb];             // attention weights [t][b]
__device__ float g_a2[Bb*256];
__device__ float g_part[Bb][8][256];

__device__ __forceinline__ float sigmf(float x){ return 1.f/(1.f+expf(-x)); }
__device__ __forceinline__ float wsum(float v){
    #pragma unroll
    for (int o=16;o;o>>=1) v += __shfl_xor_sync(0xffffffffu, v, o);
    return v;
}
__device__ __forceinline__ void fma2(unsigned long long &acc, unsigned long long a, unsigned long long b){
    asm("fma.rn.f32x2 %0, %1, %2, %0;" : "+l"(acc) : "l"(a), "l"(b));
}

// ------------- layer-1 input projection (embedding fused), both dirs -------------
__global__ __launch_bounds__(256) void k_xg1(
    const int* __restrict__ x, const float* __restrict__ emb,
    const float* __restrict__ Wf, const float* __restrict__ bf1, const float* __restrict__ bf2,
    const float* __restrict__ Wb, const float* __restrict__ bb1, const float* __restrict__ bb2)
{
    __shared__ float wf[5120], wb[5120], bf[512], bb[512], e[10];
    int b = blockIdx.y, t0 = blockIdx.x*64, tid = threadIdx.x;
    for (int i=tid;i<5120;i+=256){ wf[i]=Wf[i]; wb[i]=Wb[i]; }
    for (int i=tid;i<512;i+=256){ bf[i]=bf1[i]+bf2[i]; bb[i]=bb1[i]+bb2[i]; }
    __syncthreads();
    for (int tl=0; tl<64; tl++){
        int t = t0+tl;
        if (tid<10) e[tid] = emb[x[b*Tt+t]*10+tid];
        __syncthreads();
        float ev[10];
        #pragma unroll
        for (int d=0;d<10;d++) ev[d]=e[d];
        for (int c=tid;c<512;c+=256){
            float af=bf[c], ab=bb[c];
            #pragma unroll
            for (int d=0;d<10;d++){ af=fmaf(ev[d],wf[c*10+d],af); ab=fmaf(ev[d],wb[c*10+d],ab); }
            g_xg[0][(t*Bb+b)*512+c]=af;
            g_xg[1][(t*Bb+b)*512+c]=ab;
        }
        __syncthreads();
    }
}

// ------------- persistent bidirectional LSTM recurrence, cluster-of-2 -------------
// 128 CTAs = 64 clusters(2). cluster = (dir, batch-pair). Each CTA owns 64 hidden
// units (256 gate rows; Whh row in 128 regs/thread). h double-buffered in smem,
// exchanged with the peer CTA via DSMEM stores + barrier.cluster per step.
__global__ __launch_bounds__(256,1) __cluster_dims__(2,1,1)
void k_rec(int layer, const float* __restrict__ Whh_f, const float* __restrict__ Whh_b)
{
    __shared__ __align__(16) float hsh[2][2][128];   // [phase][batch][j]
    __shared__ float gsh[2][256];                    // [batch][g*64+kl]
    int cid = blockIdx.x>>1;
    unsigned int rank; asm("mov.u32 %0, %%cluster_ctarank;" : "=r"(rank));
    int dir = cid>>5, bpair = cid&31;
    int kb = (int)rank*64;
    int b0 = bpair*2;
    const float* Whh = dir? Whh_b : Whh_f;
    const float* xg  = g_xg[dir];
    float* out = layer? g_out2 : g_out1;
    int tid = threadIdx.x;
    int g = tid>>6, kl = tid&63;
    int grow = g*128 + kb + kl;                      // xg column == Whh row

    unsigned long long wp[64];
    {
        const float4* wr = (const float4*)&Whh[grow*128];
        #pragma unroll
        for (int i=0;i<32;i++){
            float4 w = __ldg(&wr[i]);
            asm("mov.b64 %0, {%1,%2};" : "=l"(wp[2*i])   : "f"(w.x), "f"(w.y));
            asm("mov.b64 %0, {%1,%2};" : "=l"(wp[2*i+1]) : "f"(w.z), "f"(w.w));
        }
    }
    for (int i=tid;i<512;i+=256) ((float*)hsh)[i]=0.f;

    int cbl = tid>>6, ckl = tid&63;                  // cell thread (tid<128): batch, hidden
    float cst = 0.f;

    unsigned int hbase;
    asm("{ .reg .u64 t; cvta.to.shared.u64 t, %1; cvt.u32.u64 %0, t; }" : "=r"(hbase) : "l"((void*)hsh));
    unsigned int peer_hbase;
    asm("mapa.shared::cluster.u32 %0, %1, %2;" : "=r"(peer_hbase) : "r"(hbase), "r"(rank^1u));

    __syncthreads();
    asm volatile("barrier.cluster.arrive.aligned;" ::: "memory");
    asm volatile("barrier.cluster.wait.aligned;"   ::: "memory");

    int tI = dir? 511 : 0;
    float xgc0 = __ldg(&xg[(tI*Bb + b0  )*512 + grow]);
    float xgc1 = __ldg(&xg[(tI*Bb + b0+1)*512 + grow]);
    int p = 0;

    for (int s=0; s<Tt; s++){
        int t = dir ? (511-s) : s;
        unsigned long long a0e=0ull, a0o=0ull, a1e=0ull, a1o=0ull;
        const ulonglong2* h0p = (const ulonglong2*)hsh[p][0];
        const ulonglong2* h1p = (const ulonglong2*)hsh[p][1];
        #pragma unroll
        for (int i=0;i<32;i++){
            ulonglong2 ha = h0p[i], hb = h1p[i];
            fma2(a0e, wp[2*i],   ha.x);
            fma2(a0o, wp[2*i+1], ha.y);
            fma2(a1e, wp[2*i],   hb.x);
            fma2(a1o, wp[2*i+1], hb.y);
        }
        float u0,v0,u1,v1,u2,v2,u3,v3;
        asm("mov.b64 {%0,%1}, %2;" : "=f"(u0),"=f"(v0) : "l"(a0e));
        asm("mov.b64 {%0,%1}, %2;" : "=f"(u1),"=f"(v1) : "l"(a0o));
        asm("mov.b64 {%0,%1}, %2;" : "=f"(u2),"=f"(v2) : "l"(a1e));
        asm("mov.b64 {%0,%1}, %2;" : "=f"(u3),"=f"(v3) : "l"(a1o));
        gsh[0][tid] = (u0+v0) + (u1+v1) + xgc0;
        gsh[1][tid] = (u2+v2) + (u3+v3) + xgc1;
        if (s<511){
            int tn = dir? (510-s) : (s+1);
            xgc0 = __ldg(&xg[(tn*Bb + b0  )*512 + grow]);
            xgc1 = __ldg(&xg[(tn*Bb + b0+1)*512 + grow]);
        }
        __syncthreads();
        if (tid<128){
            float gi=gsh[cbl][ckl], gf=gsh[cbl][64+ckl], gg=gsh[cbl][128+ckl], go=gsh[cbl][192+ckl];
            cst = sigmf(gf)*cst + sigmf(gi)*tanhf(gg);
            float hv = sigmf(go)*tanhf(cst);
            int k = kb + ckl;
            out[((b0+cbl)*Tt + t)*256 + dir*128 + k] = hv;
            if (s==511){
                g_h[layer][dir*Bb*128 + (b0+cbl)*128 + k] = hv;
            } else {
                int np = p^1;
                hsh[np][cbl][k] = hv;
                unsigned int off = (unsigned int)(((np*2+cbl)*128 + k)*4);
                asm volatile("st.shared::cluster.f32 [%0], %1;" :: "r"(peer_hbase+off), "f"(hv) : "memory");
            }
        }
        asm volatile("barrier.cluster.arrive.aligned;" ::: "memory");
        asm volatile("barrier.cluster.wait.aligned;"   ::: "memory");
        p ^= 1;
    }
}

// ------------- prefix gram S[b][i][t]=dot/max(i,1), 64x64 tiles, f32x2 -------------
__global__ __launch_bounds__(256) void k_gram(){
    int ti=blockIdx.x, tj=blockIdx.y, b=blockIdx.z;
    if (tj>ti) return;
    __shared__ __align__(16) float As[16][68], Bs[16][68];
    const float* O = g_out1 + (size_t)b*Tt*256;
    int i0=ti*64, t0=tj*64, tid=threadIdx.x;
    int ty=tid>>4, tx=tid&15;
    unsigned long long acc[4][2]={};
    for (int kc=0;kc<256;kc+=16){
        #pragma unroll
        for (int p=0;p<4;p++){
            int e=tid+p*256; int rr=e>>4, kk=e&15;
            As[kk][rr]=O[(i0+rr)*256+kc+kk];
            Bs[kk][rr]=O[(t0+rr)*256+kc+kk];
        }
        __syncthreads();
        #pragma unroll
        for (int kk=0;kk<16;kk++){
            float4 av=*(const float4*)&As[kk][ty*4];
            float4 bv=*(const float4*)&Bs[kk][tx*4];
            unsigned long long b01,b23,ad;
            asm("mov.b64 %0,{%1,%2};":"=l"(b01):"f"(bv.x),"f"(bv.y));
            asm("mov.b64 %0,{%1,%2};":"=l"(b23):"f"(bv.z),"f"(bv.w));
            float avq[4]={av.x,av.y,av.z,av.w};
            #pragma unroll
            for (int q=0;q<4;q++){
                asm("mov.b64 %0,{%1,%1};":"=l"(ad):"f"(avq[q]));
                fma2(acc[q][0], ad, b01);
                fma2(acc[q][1], ad, b23);
            }
        }
        __syncthreads();
    }
    #pragma unroll
    for (int q=0;q<4;q++){
        int i=i0+ty*4+q;
        float sc=1.f/(float)(i>0?i:1);
        float r0,r1,r2,r3;
        asm("mov.b64 {%0,%1},%2;":"=f"(r0),"=f"(r1):"l"(acc[q][0]));
        asm("mov.b64 {%0,%1},%2;":"=f"(r2),"=f"(r3):"l"(acc[q][1]));
        float4 res; res.x=r0*sc; res.y=r1*sc; res.z=r2*sc; res.w=r3*sc;
        *(float4*)&g_S[((size_t)b*Tt+i)*Tt+t0+tx*4] = res;
    }
}

// ------------- softmax over batch per (i,t), t<i -------------
__global__ void k_bsoft(){
    int i=blockIdx.x, t=threadIdx.x;
    if (t>=i) return;
    size_t base=(size_t)i*Tt+t;
    float v[64], m=-1e30f;
    #pragma unroll
    for (int b=0;b<64;b++){ v[b]=g_S[(size_t)b*Tt*Tt+base]; m=fmaxf(m,v[b]); }
    float s=0.f;
    #pragma unroll
    for (int b=0;b<64;b++){ v[b]=expf(v[b]-m); s+=v[b]; }
    float inv=1.f/s;
    #pragma unroll
    for (int b=0;b<64;b++) g_S[(size_t)b*Tt*Tt+base]=v[b]*inv;
}

// ------------- att[b][i][:] = sum_{t<i} W[b,i,t]*out1[b,t,:], 64x64, f32x2 -------------
__global__ __launch_bounds__(256) void k_apply(){
    int i0=blockIdx.x*64, d0=blockIdx.y*64, b=blockIdx.z;
    __shared__ __align__(16) float Ws[16][68], Os[16][68];
    const float* O=g_out1+(size_t)b*Tt*256;
    const float* W=g_S+(size_t)b*Tt*Tt;
    int tid=threadIdx.x, ty=tid>>4, tx=tid&15;
    unsigned long long acc[4][2]={};
    int kmax=i0+64;
    for (int tk=0;tk<kmax;tk+=16){
        #pragma unroll
        for (int p=0;p<4;p++){
            int e=tid+p*256; int rr=e>>4, kk=e&15;
            int tg=tk+kk;
            Ws[kk][rr] = (tg < i0+rr) ? W[(size_t)(i0+rr)*Tt+tg] : 0.f;
        }
        #pragma unroll
        for (int p=0;p<4;p++){
            int e=tid+p*256; int kk=e>>6, cc=e&63;
            Os[kk][cc]=O[(tk+kk)*256+d0+cc];
        }
        __syncthreads();
        #pragma unroll
        for (int kk=0;kk<16;kk++){
            float4 wv=*(const float4*)&Ws[kk][ty*4];
            float4 ov=*(const float4*)&Os[kk][tx*4];
            unsigned long long o01,o23,wd;
            asm("mov.b64 %0,{%1,%2};":"=l"(o01):"f"(ov.x),"f"(ov.y));
            asm("mov.b64 %0,{%1,%2};":"=l"(o23):"f"(ov.z),"f"(ov.w));
            float wq[4]={wv.x,wv.y,wv.z,wv.w};
            #pragma unroll
            for (int q=0;q<4;q++){
                asm("mov.b64 %0,{%1,%1};":"=l"(wd):"f"(wq[q]));
                fma2(acc[q][0], wd, o01);
                fma2(acc[q][1], wd, o23);
            }
        }
        __syncthreads();
    }
    float* A=g_att+(size_t)b*Tt*256;
    #pragma unroll
    for (int q=0;q<4;q++){
        int i=i0+ty*4+q;
        float r0,r1,r2,r3;
        asm("mov.b64 {%0,%1},%2;":"=f"(r0),"=f"(r1):"l"(acc[q][0]));
        asm("mov.b64 {%0,%1},%2;":"=f"(r2),"=f"(r3):"l"(acc[q][1]));
        float4 res; res.x=r0; res.y=r1; res.z=r2; res.w=r3;
        *(float4*)&A[(size_t)i*256+d0+tx*4] = res;
    }
}

// ------------- full attention: scores + softmax over batch (per t) -------------
__global__ void k_score(int layer){
    const float* O = layer? g_out2 : g_out1;
    const float* h = g_h[layer];
    int t=blockIdx.x, tid=threadIdx.x, w=tid>>5, lane=tid&31;
    __shared__ float sc[64];
    for (int j=0;j<8;j++){
        int b=w*8+j;
        const float* o=O+((size_t)b*Tt+t)*256;
        const float* hb=h+b*256;
        float a=0.f;
        for (int k=lane;k<256;k+=32) a=fmaf(o[k],hb[k],a);
        a=wsum(a);
        if (lane==0) sc[b]=a*(1.f/512.f);
    }
    __syncthreads();
    if (tid<32){
        float v0=sc[tid], v1=sc[tid+32];
        float m=fmaxf(v0,v1);
        #pragma unroll
        for (int o=16;o;o>>=1) m=fmaxf(m,__shfl_xor_sync(0xffffffffu,m,o));
        float e0=expf(v0-m), e1=expf(v1-m);
        float s=e0+e1;
        s=wsum(s);
        float inv=1.f/s;
        g_sc[t*64+tid]=e0*inv;
        g_sc[t*64+tid+32]=e1*inv;
    }
}

__global__ void k_fsum1(int layer){
    const float* O = layer? g_out2 : g_out1;
    int b=blockIdx.x, tc=blockIdx.y, d=threadIdx.x;
    const float* o=O+(size_t)b*Tt*256;
    float a=0.f;
    int t0=tc*64;
    for (int t=t0;t<t0+64;t++) a=fmaf(g_sc[t*64+b], o[t*256+d], a);
    g_part[b][tc][d]=a;
}
__global__ void k_fsum2(int layer){
    int b=blockIdx.x, d=threadIdx.x;
    float a=0.f;
    #pragma unroll
    for (int c=0;c<8;c++) a+=g_part[b][c][d];
    if (layer==0) g_att[((size_t)b*Tt+511)*256+d]=a;
    else          g_a2[b*256+d]=a;
}

// ------------- layer-2 input projection GEMM: xg2 = att @ Wih2^T + bias -------------
__global__ __launch_bounds__(256) void k_xg2(
    const float* __restrict__ Wf, const float* __restrict__ bf1, const float* __restrict__ bf2,
    const float* __restrict__ Wb, const float* __restrict__ bb1, const float* __restrict__ bb2)
{
    int mt=blockIdx.x, col0=blockIdx.y*64, dir=blockIdx.z;
    const float* W2 = dir? Wb : Wf;
    __shared__ float As[64][17], Bs[16][65], bsh[64];
    int tid=threadIdx.x;
    if (tid<64) bsh[tid] = dir? (bb1[col0+tid]+bb2[col0+tid]) : (bf1[col0+tid]+bf2[col0+tid]);
    int tx=tid&15, ty=tid>>4;
    float acc[4][4]={};
    for (int kc=0;kc<256;kc+=16){
        for (int e=tid;e<1024;e+=256){
            int rr=e>>4, kk=e&15;
            As[rr][kk]=g_att[((size_t)rr*Tt+mt)*256 + kc+kk];
        }
        {
            int e=tid; int cc=e>>2, k4=(e&3)*4;
            const float4 w = *(const float4*)&W2[(col0+cc)*256 + kc+k4];
            Bs[k4][cc]=w.x; Bs[k4+1][cc]=w.y; Bs[k4+2][cc]=w.z; Bs[k4+3][cc]=w.w;
        }
        __syncthreads();
        #pragma unroll
        for (int kk=0;kk<16;kk++){
            float av[4], bv[4];
            #pragma unroll
            for (int q=0;q<4;q++){ av[q]=As[ty*4+q][kk]; bv[q]=Bs[kk][tx*4+q]; }
            #pragma unroll
            for (int q=0;q<4;q++)
                #pragma unroll
                for (int j=0;j<4;j++) acc[q][j]=fmaf(av[q],bv[j],acc[q][j]);
        }
        __syncthreads();
    }
    #pragma unroll
    for (int q=0;q<4;q++){
        int b=ty*4+q;
        #pragma unroll
        for (int j=0;j<4;j++){
            int c=col0+tx*4+j;
            g_xg[dir][(mt*64+b)*512 + c] = acc[q][j] + bsh[tx*4+j];
        }
    }
}

__global__ void k_final(const float* __restrict__ W, const float* __restrict__ bb, float* out){
    __shared__ float w[256];
    int tid=threadIdx.x;
    for (int i=tid;i<256;i+=64) w[i]=W[i];
    __syncthreads();
    float a=bb[0];
    for (int k=0;k<256;k++) a=fmaf(g_a2[tid*256+k],w[k],a);
    out[tid]=1.f/(1.f+expf(-a));
}

extern "C" void kernel_launch(void* const* d_in, const int* in_sizes, int n_in,
                              void* d_out, int out_size)
{
    const int*   x   = (const int*)  d_in[0];
    const float* emb = (const float*)d_in[1];
    const float* l1Wihf=(const float*)d_in[2],  *l1Whhf=(const float*)d_in[3];
    const float* l1bihf=(const float*)d_in[4],  *l1bhhf=(const float*)d_in[5];
    const float* l1Wihb=(const float*)d_in[6],  *l1Whhb=(const float*)d_in[7];
    const float* l1bihb=(const float*)d_in[8],  *l1bhhb=(const float*)d_in[9];
    const float* l2Wihf=(const float*)d_in[10], *l2Whhf=(const float*)d_in[11];
    const float* l2bihf=(const float*)d_in[12], *l2bhhf=(const float*)d_in[13];
    const float* l2Wihb=(const float*)d_in[14], *l2Whhb=(const float*)d_in[15];
    const float* l2bihb=(const float*)d_in[16], *l2bhhb=(const float*)d_in[17];
    const float* linW=(const float*)d_in[18],   *linb=(const float*)d_in[19];
    float* out=(float*)d_out;

    k_xg1<<<dim3(8,64),256>>>(x,emb,l1Wihf,l1bihf,l1bhhf,l1Wihb,l1bihb,l1bhhb);
    k_rec<<<128,256>>>(0,l1Whhf,l1Whhb);
    k_gram<<<dim3(8,8,64),256>>>();
    k_bsoft<<<512,512>>>();
    k_apply<<<dim3(8,4,64),256>>>();
    k_score<<<512,256>>>(0);
    k_fsum1<<<dim3(64,8),256>>>(0);
    k_fsum2<<<64,256>>>(0);
    k_xg2<<<dim3(512,8,2),256>>>(l2Wihf,l2bihf,l2bhhf,l2Wihb,l2bihb,l2bhhb);
    k_rec<<<128,256>>>(1,l2Whhf,l2Whhb);
    k_score<<<512,256>>>(1);
    k_fsum1<<<dim3(64,8),256>>>(1);
    k_fsum2<<<64,256>>>(1);
    k_final<<<1,64>>>(linW,linb,out);
}

// round 8
// speedup vs baseline: 2.3865x; 1.2614x over previous
#include <cuda_runtime.h>
#include <stdint.h>
#include <math.h>

#define Tt 512
#define Bb 64

// ------------- static device scratch -------------
__device__ float g_xg[2][Tt*Bb*512];      // [dir][(t*64+b)*512+col], reused across layers
__device__ float g_out1[Bb*Tt*256];
__device__ float g_out2[Bb*Tt*256];
__device__ float g_att[Bb*Tt*256];
__device__ float g_S[(size_t)Bb*Tt*Tt];   // gram -> softmaxed weights in place
__device__ float g_h[2][2*Bb*128];        // [layer][dir*B*H + b*H + k]
__device__ float g_sc[Tt*Bb];             // attention weights [t][b]
__device__ float g_a2[Bb*256];
__device__ float g_part[Bb][8][256];

__device__ __forceinline__ float sigmf(float x){ return 1.f/(1.f+expf(-x)); }
__device__ __forceinline__ float wsum(float v){
    #pragma unroll
    for (int o=16;o;o>>=1) v += __shfl_xor_sync(0xffffffffu, v, o);
    return v;
}
__device__ __forceinline__ void fma2(unsigned long long &acc, unsigned long long a, unsigned long long b){
    asm("fma.rn.f32x2 %0, %1, %2, %0;" : "+l"(acc) : "l"(a), "l"(b));
}

// ------------- layer-1 input projection (embedding fused), both dirs -------------
__global__ __launch_bounds__(256) void k_xg1(
    const int* __restrict__ x, const float* __restrict__ emb,
    const float* __restrict__ Wf, const float* __restrict__ bf1, const float* __restrict__ bf2,
    const float* __restrict__ Wb, const float* __restrict__ bb1, const float* __restrict__ bb2)
{
    __shared__ float wf[5120], wb[5120], bf[512], bb[512], e[10];
    int b = blockIdx.y, t0 = blockIdx.x*64, tid = threadIdx.x;
    for (int i=tid;i<5120;i+=256){ wf[i]=Wf[i]; wb[i]=Wb[i]; }
    for (int i=tid;i<512;i+=256){ bf[i]=bf1[i]+bf2[i]; bb[i]=bb1[i]+bb2[i]; }
    __syncthreads();
    for (int tl=0; tl<64; tl++){
        int t = t0+tl;
        if (tid<10) e[tid] = emb[x[b*Tt+t]*10+tid];
        __syncthreads();
        float ev[10];
        #pragma unroll
        for (int d=0;d<10;d++) ev[d]=e[d];
        for (int c=tid;c<512;c+=256){
            float af=bf[c], ab=bb[c];
            #pragma unroll
            for (int d=0;d<10;d++){ af=fmaf(ev[d],wf[c*10+d],af); ab=fmaf(ev[d],wb[c*10+d],ab); }
            g_xg[0][(t*Bb+b)*512+c]=af;
            g_xg[1][(t*Bb+b)*512+c]=ab;
        }
        __syncthreads();
    }
}

// ------------- persistent bidirectional LSTM recurrence, cluster-of-2 -------------
// 128 CTAs = 64 clusters(2). cluster = (dir, batch-pair). Each CTA owns 64 hidden
// units (256 gate rows; Whh row in 128 regs/thread). h double-buffered in smem;
// peer half delivered via st.shared::cluster + per-phase mbarrier (count=128),
// replacing the per-step cluster.sync (saves ~300cyc/step + keeps L1 warm).
__global__ __launch_bounds__(256,1) __cluster_dims__(2,1,1)
void k_rec(int layer, const float* __restrict__ Whh_f, const float* __restrict__ Whh_b)
{
    __shared__ __align__(16) float hsh[2][2][128];   // [phase][batch][j]
    __shared__ float gsh[2][256];                    // [batch][g*64+kl]
    __shared__ __align__(8) unsigned long long mbar[2];
    int cid = blockIdx.x>>1;
    unsigned int rank; asm("mov.u32 %0, %%cluster_ctarank;" : "=r"(rank));
    int dir = cid>>5, bpair = cid&31;
    int kb = (int)rank*64;
    int b0 = bpair*2;
    const float* Whh = dir? Whh_b : Whh_f;
    const float* xg  = g_xg[dir];
    float* out = layer? g_out2 : g_out1;
    int tid = threadIdx.x;
    int g = tid>>6, kl = tid&63;
    int grow = g*128 + kb + kl;                      // xg column == Whh row

    unsigned long long wp[64];
    {
        const float4* wr = (const float4*)&Whh[grow*128];
        #pragma unroll
        for (int i=0;i<32;i++){
            float4 w = __ldg(&wr[i]);
            asm("mov.b64 %0, {%1,%2};" : "=l"(wp[2*i])   : "f"(w.x), "f"(w.y));
            asm("mov.b64 %0, {%1,%2};" : "=l"(wp[2*i+1]) : "f"(w.z), "f"(w.w));
        }
    }
    for (int i=tid;i<512;i+=256) ((float*)hsh)[i]=0.f;

    int cbl = tid>>6, ckl = tid&63;                  // cell thread (tid<128): batch, hidden
    float cst = 0.f;

    unsigned int hbase;
    asm("{ .reg .u64 t; cvta.to.shared.u64 t, %1; cvt.u32.u64 %0, t; }" : "=r"(hbase) : "l"((void*)hsh));
    unsigned int mbase;
    asm("{ .reg .u64 t; cvta.to.shared.u64 t, %1; cvt.u32.u64 %0, t; }" : "=r"(mbase) : "l"((void*)mbar));
    if (tid==0){
        asm volatile("mbarrier.init.shared.b64 [%0], %1;" :: "r"(mbase),   "r"(128u) : "memory");
        asm volatile("mbarrier.init.shared.b64 [%0], %1;" :: "r"(mbase+8), "r"(128u) : "memory");
    }
    unsigned int peer_hbase, peer_mbase;
    asm("mapa.shared::cluster.u32 %0, %1, %2;" : "=r"(peer_hbase) : "r"(hbase), "r"(rank^1u));
    asm("mapa.shared::cluster.u32 %0, %1, %2;" : "=r"(peer_mbase) : "r"(mbase), "r"(rank^1u));

    __syncthreads();
    asm volatile("barrier.cluster.arrive.aligned;" ::: "memory");
    asm volatile("barrier.cluster.wait.aligned;"   ::: "memory");

    int tI = dir? 511 : 0;
    float xgc0 = __ldg(&xg[(tI*Bb + b0  )*512 + grow]);
    float xgc1 = __ldg(&xg[(tI*Bb + b0+1)*512 + grow]);
    int p = 0;
    int par0 = 0, par1 = 0;

    for (int s=0; s<Tt; s++){
        int t = dir ? (511-s) : s;
        unsigned long long a0e=0ull, a0o=0ull, a1e=0ull, a1o=0ull;
        const ulonglong2* h0p = (const ulonglong2*)hsh[p][0];
        const ulonglong2* h1p = (const ulonglong2*)hsh[p][1];
        #pragma unroll
        for (int i=0;i<32;i++){
            ulonglong2 ha = h0p[i], hb = h1p[i];
            fma2(a0e, wp[2*i],   ha.x);
            fma2(a0o, wp[2*i+1], ha.y);
            fma2(a1e, wp[2*i],   hb.x);
            fma2(a1o, wp[2*i+1], hb.y);
        }
        float u0,v0,u1,v1,u2,v2,u3,v3;
        asm("mov.b64 {%0,%1}, %2;" : "=f"(u0),"=f"(v0) : "l"(a0e));
        asm("mov.b64 {%0,%1}, %2;" : "=f"(u1),"=f"(v1) : "l"(a0o));
        asm("mov.b64 {%0,%1}, %2;" : "=f"(u2),"=f"(v2) : "l"(a1e));
        asm("mov.b64 {%0,%1}, %2;" : "=f"(u3),"=f"(v3) : "l"(a1o));
        gsh[0][tid] = (u0+v0) + (u1+v1) + xgc0;
        gsh[1][tid] = (u2+v2) + (u3+v3) + xgc1;
        if (s<511){
            int tn = dir? (510-s) : (s+1);
            xgc0 = __ldg(&xg[(tn*Bb + b0  )*512 + grow]);
            xgc1 = __ldg(&xg[(tn*Bb + b0+1)*512 + grow]);
        }
        __syncthreads();
        int np = p^1;
        if (tid<128){
            float gi=gsh[cbl][ckl], gf=gsh[cbl][64+ckl], gg=gsh[cbl][128+ckl], go=gsh[cbl][192+ckl];
            cst = sigmf(gf)*cst + sigmf(gi)*tanhf(gg);
            float hv = sigmf(go)*tanhf(cst);
            int k = kb + ckl;
            out[((b0+cbl)*Tt + t)*256 + dir*128 + k] = hv;
            if (s==511){
                g_h[layer][dir*Bb*128 + (b0+cbl)*128 + k] = hv;
            } else {
                hsh[np][cbl][k] = hv;
                unsigned int off = (unsigned int)(((np*2+cbl)*128 + k)*4);
                asm volatile("st.shared::cluster.f32 [%0], %1;" :: "r"(peer_hbase+off), "f"(hv) : "memory");
                asm volatile("mbarrier.arrive.shared::cluster.b64 _, [%0];" :: "r"(peer_mbase + (unsigned)np*8u) : "memory");
            }
        }
        if (s<511){
            int ph = np ? par1 : par0;
            unsigned int mbaddr = mbase + (unsigned)np*8u;
            unsigned int done;
            asm volatile(
                "{\n\t.reg .pred p;\n\t"
                "mbarrier.try_wait.parity.acquire.cluster.shared::cta.b64 p, [%1], %2;\n\t"
                "selp.b32 %0, 1, 0, p;\n\t}"
                : "=r"(done) : "r"(mbaddr), "r"((unsigned)ph) : "memory");
            while (!done){
                asm volatile(
                    "{\n\t.reg .pred p;\n\t"
                    "mbarrier.try_wait.parity.acquire.cluster.shared::cta.b64 p, [%1], %2, 0x989680;\n\t"
                    "selp.b32 %0, 1, 0, p;\n\t}"
                    : "=r"(done) : "r"(mbaddr), "r"((unsigned)ph) : "memory");
            }
            if (np) par1^=1; else par0^=1;
            __syncthreads();
        }
        p ^= 1;
    }
    asm volatile("barrier.cluster.arrive.aligned;" ::: "memory");
    asm volatile("barrier.cluster.wait.aligned;"   ::: "memory");
}

// ------------- prefix gram S[b][i][t]=dot/max(i,1), 64x64 tiles, f32x2 -------------
__global__ __launch_bounds__(256) void k_gram(){
    int ti=blockIdx.x, tj=blockIdx.y, b=blockIdx.z;
    if (tj>ti) return;
    __shared__ __align__(16) float As[16][68], Bs[16][68];
    const float* O = g_out1 + (size_t)b*Tt*256;
    int i0=ti*64, t0=tj*64, tid=threadIdx.x;
    int ty=tid>>4, tx=tid&15;
    unsigned long long acc[4][2]={};
    for (int kc=0;kc<256;kc+=16){
        #pragma unroll
        for (int p=0;p<4;p++){
            int e=tid+p*256; int rr=e>>4, kk=e&15;
            As[kk][rr]=O[(i0+rr)*256+kc+kk];
            Bs[kk][rr]=O[(t0+rr)*256+kc+kk];
        }
        __syncthreads();
        #pragma unroll
        for (int kk=0;kk<16;kk++){
            float4 av=*(const float4*)&As[kk][ty*4];
            float4 bv=*(const float4*)&Bs[kk][tx*4];
            unsigned long long b01,b23,ad;
            asm("mov.b64 %0,{%1,%2};":"=l"(b01):"f"(bv.x),"f"(bv.y));
            asm("mov.b64 %0,{%1,%2};":"=l"(b23):"f"(bv.z),"f"(bv.w));
            float avq[4]={av.x,av.y,av.z,av.w};
            #pragma unroll
            for (int q=0;q<4;q++){
                asm("mov.b64 %0,{%1,%1};":"=l"(ad):"f"(avq[q]));
                fma2(acc[q][0], ad, b01);
                fma2(acc[q][1], ad, b23);
            }
        }
        __syncthreads();
    }
    #pragma unroll
    for (int q=0;q<4;q++){
        int i=i0+ty*4+q;
        float sc=1.f/(float)(i>0?i:1);
        float r0,r1,r2,r3;
        asm("mov.b64 {%0,%1},%2;":"=f"(r0),"=f"(r1):"l"(acc[q][0]));
        asm("mov.b64 {%0,%1},%2;":"=f"(r2),"=f"(r3):"l"(acc[q][1]));
        float4 res; res.x=r0*sc; res.y=r1*sc; res.z=r2*sc; res.w=r3*sc;
        *(float4*)&g_S[((size_t)b*Tt+i)*Tt+t0+tx*4] = res;
    }
}

// ------------- softmax over batch per (i,t), t<i -------------
__global__ void k_bsoft(){
    int i=blockIdx.x, t=threadIdx.x;
    if (t>=i) return;
    size_t base=(size_t)i*Tt+t;
    float v[64], m=-1e30f;
    #pragma unroll
    for (int b=0;b<64;b++){ v[b]=g_S[(size_t)b*Tt*Tt+base]; m=fmaxf(m,v[b]); }
    float s=0.f;
    #pragma unroll
    for (int b=0;b<64;b++){ v[b]=expf(v[b]-m); s+=v[b]; }
    float inv=1.f/s;
    #pragma unroll
    for (int b=0;b<64;b++) g_S[(size_t)b*Tt*Tt+base]=v[b]*inv;
}

// ------------- att[b][i][:] = sum_{t<i} W[b,i,t]*out1[b,t,:], 64x64, f32x2 -------------
__global__ __launch_bounds__(256) void k_apply(){
    int i0=blockIdx.x*64, d0=blockIdx.y*64, b=blockIdx.z;
    __shared__ __align__(16) float Ws[16][68], Os[16][68];
    const float* O=g_out1+(size_t)b*Tt*256;
    const float* W=g_S+(size_t)b*Tt*Tt;
    int tid=threadIdx.x, ty=tid>>4, tx=tid&15;
    unsigned long long acc[4][2]={};
    int kmax=i0+64;
    for (int tk=0;tk<kmax;tk+=16){
        #pragma unroll
        for (int p=0;p<4;p++){
            int e=tid+p*256; int rr=e>>4, kk=e&15;
            int tg=tk+kk;
            Ws[kk][rr] = (tg < i0+rr) ? W[(size_t)(i0+rr)*Tt+tg] : 0.f;
        }
        #pragma unroll
        for (int p=0;p<4;p++){
            int e=tid+p*256; int kk=e>>6, cc=e&63;
            Os[kk][cc]=O[(tk+kk)*256+d0+cc];
        }
        __syncthreads();
        #pragma unroll
        for (int kk=0;kk<16;kk++){
            float4 wv=*(const float4*)&Ws[kk][ty*4];
            float4 ov=*(const float4*)&Os[kk][tx*4];
            unsigned long long o01,o23,wd;
            asm("mov.b64 %0,{%1,%2};":"=l"(o01):"f"(ov.x),"f"(ov.y));
            asm("mov.b64 %0,{%1,%2};":"=l"(o23):"f"(ov.z),"f"(ov.w));
            float wq[4]={wv.x,wv.y,wv.z,wv.w};
            #pragma unroll
            for (int q=0;q<4;q++){
                asm("mov.b64 %0,{%1,%1};":"=l"(wd):"f"(wq[q]));
                fma2(acc[q][0], wd, o01);
                fma2(acc[q][1], wd, o23);
            }
        }
        __syncthreads();
    }
    float* A=g_att+(size_t)b*Tt*256;
    #pragma unroll
    for (int q=0;q<4;q++){
        int i=i0+ty*4+q;
        float r0,r1,r2,r3;
        asm("mov.b64 {%0,%1},%2;":"=f"(r0),"=f"(r1):"l"(acc[q][0]));
        asm("mov.b64 {%0,%1},%2;":"=f"(r2),"=f"(r3):"l"(acc[q][1]));
        float4 res; res.x=r0; res.y=r1; res.z=r2; res.w=r3;
        *(float4*)&A[(size_t)i*256+d0+tx*4] = res;
    }
}

// ------------- full attention: scores + softmax over batch (per t) -------------
__global__ void k_score(int layer){
    const float* O = layer? g_out2 : g_out1;
    const float* h = g_h[layer];
    int t=blockIdx.x, tid=threadIdx.x, w=tid>>5, lane=tid&31;
    __shared__ float sc[64];
    for (int j=0;j<8;j++){
        int b=w*8+j;
        const float* o=O+((size_t)b*Tt+t)*256;
        const float* hb=h+b*256;
        float a=0.f;
        for (int k=lane;k<256;k+=32) a=fmaf(o[k],hb[k],a);
        a=wsum(a);
        if (lane==0) sc[b]=a*(1.f/512.f);
    }
    __syncthreads();
    if (tid<32){
        float v0=sc[tid], v1=sc[tid+32];
        float m=fmaxf(v0,v1);
        #pragma unroll
        for (int o=16;o;o>>=1) m=fmaxf(m,__shfl_xor_sync(0xffffffffu,m,o));
        float e0=expf(v0-m), e1=expf(v1-m);
        float s=e0+e1;
        s=wsum(s);
        float inv=1.f/s;
        g_sc[t*64+tid]=e0*inv;
        g_sc[t*64+tid+32]=e1*inv;
    }
}

__global__ void k_fsum1(int layer){
    const float* O = layer? g_out2 : g_out1;
    int b=blockIdx.x, tc=blockIdx.y, d=threadIdx.x;
    const float* o=O+(size_t)b*Tt*256;
    float a=0.f;
    int t0=tc*64;
    for (int t=t0;t<t0+64;t++) a=fmaf(g_sc[t*64+b], o[t*256+d], a);
    g_part[b][tc][d]=a;
}
__global__ void k_fsum2(int layer){
    int b=blockIdx.x, d=threadIdx.x;
    float a=0.f;
    #pragma unroll
    for (int c=0;c<8;c++) a+=g_part[b][c][d];
    if (layer==0) g_att[((size_t)b*Tt+511)*256+d]=a;
    else          g_a2[b*256+d]=a;
}

// ------------- layer-2 input projection GEMM: xg2 = att @ Wih2^T + bias, f32x2 -------------
__global__ __launch_bounds__(256) void k_xg2(
    const float* __restrict__ Wf, const float* __restrict__ bf1, const float* __restrict__ bf2,
    const float* __restrict__ Wb, const float* __restrict__ bb1, const float* __restrict__ bb2)
{
    int t0=blockIdx.x*64, col0=blockIdx.y*64;
    int z=blockIdx.z; int b=z>>1, dir=z&1;
    const float* W2 = dir? Wb : Wf;
    __shared__ __align__(16) float As[16][68], Bs[16][68];
    __shared__ float bsh[64];
    int tid=threadIdx.x, ty=tid>>4, tx=tid&15;
    if (tid<64) bsh[tid] = dir? (bb1[col0+tid]+bb2[col0+tid]) : (bf1[col0+tid]+bf2[col0+tid]);
    const float* A = g_att + (size_t)b*Tt*256;
    unsigned long long acc[4][2]={};
    for (int kc=0;kc<256;kc+=16){
        #pragma unroll
        for (int pq=0;pq<4;pq++){
            int e=tid+pq*256; int rr=e>>4, kk=e&15;
            As[kk][rr]=A[(t0+rr)*256+kc+kk];
            Bs[kk][rr]=W2[(col0+rr)*256+kc+kk];
        }
        __syncthreads();
        #pragma unroll
        for (int kk=0;kk<16;kk++){
            float4 av=*(const float4*)&As[kk][ty*4];
            float4 bv=*(const float4*)&Bs[kk][tx*4];
            unsigned long long b01,b23,ad;
            asm("mov.b64 %0,{%1,%2};":"=l"(b01):"f"(bv.x),"f"(bv.y));
            asm("mov.b64 %0,{%1,%2};":"=l"(b23):"f"(bv.z),"f"(bv.w));
            float avq[4]={av.x,av.y,av.z,av.w};
            #pragma unroll
            for (int q=0;q<4;q++){
                asm("mov.b64 %0,{%1,%1};":"=l"(ad):"f"(avq[q]));
                fma2(acc[q][0], ad, b01);
                fma2(acc[q][1], ad, b23);
            }
        }
        __syncthreads();
    }
    #pragma unroll
    for (int q=0;q<4;q++){
        int t=t0+ty*4+q;
        float r0,r1,r2,r3;
        asm("mov.b64 {%0,%1},%2;":"=f"(r0),"=f"(r1):"l"(acc[q][0]));
        asm("mov.b64 {%0,%1},%2;":"=f"(r2),"=f"(r3):"l"(acc[q][1]));
        float4 res;
        res.x=r0+bsh[tx*4+0]; res.y=r1+bsh[tx*4+1];
        res.z=r2+bsh[tx*4+2]; res.w=r3+bsh[tx*4+3];
        *(float4*)&g_xg[dir][(t*Bb+b)*512 + col0 + tx*4] = res;
    }
}

__global__ void k_final(const float* __restrict__ W, const float* __restrict__ bb, float* out){
    __shared__ float w[256];
    int tid=threadIdx.x;
    for (int i=tid;i<256;i+=64) w[i]=W[i];
    __syncthreads();
    float a=bb[0];
    for (int k=0;k<256;k++) a=fmaf(g_a2[tid*256+k],w[k],a);
    out[tid]=1.f/(1.f+expf(-a));
}

extern "C" void kernel_launch(void* const* d_in, const int* in_sizes, int n_in,
                              void* d_out, int out_size)
{
    const int*   x   = (const int*)  d_in[0];
    const float* emb = (const float*)d_in[1];
    const float* l1Wihf=(const float*)d_in[2],  *l1Whhf=(const float*)d_in[3];
    const float* l1bihf=(const float*)d_in[4],  *l1bhhf=(const float*)d_in[5];
    const float* l1Wihb=(const float*)d_in[6],  *l1Whhb=(const float*)d_in[7];
    const float* l1bihb=(const float*)d_in[8],  *l1bhhb=(const float*)d_in[9];
    const float* l2Wihf=(const float*)d_in[10], *l2Whhf=(const float*)d_in[11];
    const float* l2bihf=(const float*)d_in[12], *l2bhhf=(const float*)d_in[13];
    const float* l2Wihb=(const float*)d_in[14], *l2Whhb=(const float*)d_in[15];
    const float* l2bihb=(const float*)d_in[16], *l2bhhb=(const float*)d_in[17];
    const float* linW=(const float*)d_in[18],   *linb=(const float*)d_in[19];
    float* out=(float*)d_out;

    k_xg1<<<dim3(8,64),256>>>(x,emb,l1Wihf,l1bihf,l1bhhf,l1Wihb,l1bihb,l1bhhb);
    k_rec<<<128,256>>>(0,l1Whhf,l1Whhb);
    k_gram<<<dim3(8,8,64),256>>>();
    k_bsoft<<<512,512>>>();
    k_apply<<<dim3(8,4,64),256>>>();
    k_score<<<512,256>>>(0);
    k_fsum1<<<dim3(64,8),256>>>(0);
    k_fsum2<<<64,256>>>(0);
    k_xg2<<<dim3(8,8,128),256>>>(l2Wihf,l2bihf,l2bhhf,l2Wihb,l2bihb,l2bhhb);
    k_rec<<<128,256>>>(1,l2Whhf,l2Whhb);
    k_score<<<512,256>>>(1);
    k_fsum1<<<dim3(64,8),256>>>(1);
    k_fsum2<<<64,256>>>(1);
    k_final<<<1,64>>>(linW,linb,out);
}

// round 9
// speedup vs baseline: 2.4813x; 1.0397x over previous
#include <cuda_runtime.h>
#include <stdint.h>
#include <math.h>

#define Tt 512
#define Bb 64

// ------------- static device scratch -------------
__device__ float g_xg[2][Tt*Bb*512];      // [dir][(t*64+b)*512+col], reused across layers
__device__ float g_out1[Bb*Tt*256];
__device__ float g_out2[Bb*Tt*256];
__device__ float g_att[Bb*Tt*256];
__device__ float g_S[(size_t)Bb*Tt*Tt];   // gram -> softmaxed weights in place
__device__ float g_h[2][2*Bb*128];        // [layer][dir*B*H + b*H + k]
__device__ float g_sc[Tt*Bb];             // attention weights [t][b]
__device__ float g_a2[Bb*256];
__device__ float g_part[Bb][8][256];

__device__ __forceinline__ float sigm_fast(float x){ return __fdividef(1.f, 1.f + __expf(-x)); }
__device__ __forceinline__ float tanh_fast(float x){ return 1.f - __fdividef(2.f, __expf(2.f*x) + 1.f); }
__device__ __forceinline__ float wsum(float v){
    #pragma unroll
    for (int o=16;o;o>>=1) v += __shfl_xor_sync(0xffffffffu, v, o);
    return v;
}
__device__ __forceinline__ void fma2(unsigned long long &acc, unsigned long long a, unsigned long long b){
    asm("fma.rn.f32x2 %0, %1, %2, %0;" : "+l"(acc) : "l"(a), "l"(b));
}

// ------------- layer-1 input projection (embedding fused), both dirs -------------
__global__ __launch_bounds__(256) void k_xg1(
    const int* __restrict__ x, const float* __restrict__ emb,
    const float* __restrict__ Wf, const float* __restrict__ bf1, const float* __restrict__ bf2,
    const float* __restrict__ Wb, const float* __restrict__ bb1, const float* __restrict__ bb2)
{
    __shared__ float wf[5120], wb[5120], bf[512], bb[512], e[10];
    int b = blockIdx.y, t0 = blockIdx.x*64, tid = threadIdx.x;
    for (int i=tid;i<5120;i+=256){ wf[i]=Wf[i]; wb[i]=Wb[i]; }
    for (int i=tid;i<512;i+=256){ bf[i]=bf1[i]+bf2[i]; bb[i]=bb1[i]+bb2[i]; }
    __syncthreads();
    for (int tl=0; tl<64; tl++){
        int t = t0+tl;
        if (tid<10) e[tid] = emb[x[b*Tt+t]*10+tid];
        __syncthreads();
        float ev[10];
        #pragma unroll
        for (int d=0;d<10;d++) ev[d]=e[d];
        for (int c=tid;c<512;c+=256){
            float af=bf[c], ab=bb[c];
            #pragma unroll
            for (int d=0;d<10;d++){ af=fmaf(ev[d],wf[c*10+d],af); ab=fmaf(ev[d],wb[c*10+d],ab); }
            g_xg[0][(t*Bb+b)*512+c]=af;
            g_xg[1][(t*Bb+b)*512+c]=ab;
        }
        __syncthreads();
    }
}

// ------------- persistent bidirectional LSTM recurrence, cluster-of-2 -------------
// 128 CTAs = 64 clusters(2). cluster = (dir, batch-pair). Each CTA owns 64 hidden
// units (256 gate rows; Whh row in 128 regs/thread). h double-buffered in smem;
// peer half delivered via st.shared::cluster + per-phase mbarrier (count=128).
// Gate activations use fast MUFU forms (exact saturation, ~1e-6 rel err).
__global__ __launch_bounds__(256,1) __cluster_dims__(2,1,1)
void k_rec(int layer, const float* __restrict__ Whh_f, const float* __restrict__ Whh_b)
{
    __shared__ __align__(16) float hsh[2][2][128];   // [phase][batch][j]
    __shared__ float gsh[2][256];                    // [batch][g*64+kl]
    __shared__ __align__(8) unsigned long long mbar[2];
    int cid = blockIdx.x>>1;
    unsigned int rank; asm("mov.u32 %0, %%cluster_ctarank;" : "=r"(rank));
    int dir = cid>>5, bpair = cid&31;
    int kb = (int)rank*64;
    int b0 = bpair*2;
    const float* Whh = dir? Whh_b : Whh_f;
    const float* xg  = g_xg[dir];
    float* out = layer? g_out2 : g_out1;
    int tid = threadIdx.x;
    int g = tid>>6, kl = tid&63;
    int grow = g*128 + kb + kl;                      // xg column == Whh row

    unsigned long long wp[64];
    {
        const float4* wr = (const float4*)&Whh[grow*128];
        #pragma unroll
        for (int i=0;i<32;i++){
            float4 w = __ldg(&wr[i]);
            asm("mov.b64 %0, {%1,%2};" : "=l"(wp[2*i])   : "f"(w.x), "f"(w.y));
            asm("mov.b64 %0, {%1,%2};" : "=l"(wp[2*i+1]) : "f"(w.z), "f"(w.w));
        }
    }
    for (int i=tid;i<512;i+=256) ((float*)hsh)[i]=0.f;

    int cbl = tid>>6, ckl = tid&63;                  // cell thread (tid<128): batch, hidden
    float cst = 0.f;

    unsigned int hbase;
    asm("{ .reg .u64 t; cvta.to.shared.u64 t, %1; cvt.u32.u64 %0, t; }" : "=r"(hbase) : "l"((void*)hsh));
    unsigned int mbase;
    asm("{ .reg .u64 t; cvta.to.shared.u64 t, %1; cvt.u32.u64 %0, t; }" : "=r"(mbase) : "l"((void*)mbar));
    if (tid==0){
        asm volatile("mbarrier.init.shared.b64 [%0], %1;" :: "r"(mbase),   "r"(128u) : "memory");
        asm volatile("mbarrier.init.shared.b64 [%0], %1;" :: "r"(mbase+8), "r"(128u) : "memory");
    }
    unsigned int peer_hbase, peer_mbase;
    asm("mapa.shared::cluster.u32 %0, %1, %2;" : "=r"(peer_hbase) : "r"(hbase), "r"(rank^1u));
    asm("mapa.shared::cluster.u32 %0, %1, %2;" : "=r"(peer_mbase) : "r"(mbase), "r"(rank^1u));

    __syncthreads();
    asm volatile("barrier.cluster.arrive.aligned;" ::: "memory");
    asm volatile("barrier.cluster.wait.aligned;"   ::: "memory");

    int tI = dir? 511 : 0;
    float xgc0 = __ldg(&xg[(tI*Bb + b0  )*512 + grow]);
    float xgc1 = __ldg(&xg[(tI*Bb + b0+1)*512 + grow]);
    int p = 0;
    int par0 = 0, par1 = 0;

    for (int s=0; s<Tt; s++){
        int t = dir ? (511-s) : s;
        unsigned long long a0e=0ull, a0o=0ull, a1e=0ull, a1o=0ull;
        const ulonglong2* h0p = (const ulonglong2*)hsh[p][0];
        const ulonglong2* h1p = (const ulonglong2*)hsh[p][1];
        #pragma unroll
        for (int i=0;i<32;i++){
            ulonglong2 ha = h0p[i], hb = h1p[i];
            fma2(a0e, wp[2*i],   ha.x);
            fma2(a0o, wp[2*i+1], ha.y);
            fma2(a1e, wp[2*i],   hb.x);
            fma2(a1o, wp[2*i+1], hb.y);
        }
        float u0,v0,u1,v1,u2,v2,u3,v3;
        asm("mov.b64 {%0,%1}, %2;" : "=f"(u0),"=f"(v0) : "l"(a0e));
        asm("mov.b64 {%0,%1}, %2;" : "=f"(u1),"=f"(v1) : "l"(a0o));
        asm("mov.b64 {%0,%1}, %2;" : "=f"(u2),"=f"(v2) : "l"(a1e));
        asm("mov.b64 {%0,%1}, %2;" : "=f"(u3),"=f"(v3) : "l"(a1o));
        gsh[0][tid] = (u0+v0) + (u1+v1) + xgc0;
        gsh[1][tid] = (u2+v2) + (u3+v3) + xgc1;
        if (s<511){
            int tn = dir? (510-s) : (s+1);
            xgc0 = __ldg(&xg[(tn*Bb + b0  )*512 + grow]);
            xgc1 = __ldg(&xg[(tn*Bb + b0+1)*512 + grow]);
        }
        __syncthreads();
        int np = p^1;
        if (tid<128){
            float gi=gsh[cbl][ckl], gf=gsh[cbl][64+ckl], gg=gsh[cbl][128+ckl], go=gsh[cbl][192+ckl];
            cst = sigm_fast(gf)*cst + sigm_fast(gi)*tanh_fast(gg);
            float hv = sigm_fast(go)*tanh_fast(cst);
            int k = kb + ckl;
            out[((b0+cbl)*Tt + t)*256 + dir*128 + k] = hv;
            if (s==511){
                g_h[layer][dir*Bb*128 + (b0+cbl)*128 + k] = hv;
            } else {
                hsh[np][cbl][k] = hv;
                unsigned int off = (unsigned int)(((np*2+cbl)*128 + k)*4);
                asm volatile("st.shared::cluster.f32 [%0], %1;" :: "r"(peer_hbase+off), "f"(hv) : "memory");
                asm volatile("mbarrier.arrive.shared::cluster.b64 _, [%0];" :: "r"(peer_mbase + (unsigned)np*8u) : "memory");
            }
        }
        if (s<511){
            int ph = np ? par1 : par0;
            unsigned int mbaddr = mbase + (unsigned)np*8u;
            unsigned int done;
            asm volatile(
                "{\n\t.reg .pred p;\n\t"
                "mbarrier.try_wait.parity.acquire.cluster.shared::cta.b64 p, [%1], %2;\n\t"
                "selp.b32 %0, 1, 0, p;\n\t}"
                : "=r"(done) : "r"(mbaddr), "r"((unsigned)ph) : "memory");
            while (!done){
                asm volatile(
                    "{\n\t.reg .pred p;\n\t"
                    "mbarrier.try_wait.parity.acquire.cluster.shared::cta.b64 p, [%1], %2, 0x989680;\n\t"
                    "selp.b32 %0, 1, 0, p;\n\t}"
                    : "=r"(done) : "r"(mbaddr), "r"((unsigned)ph) : "memory");
            }
            if (np) par1^=1; else par0^=1;
            __syncthreads();
        }
        p ^= 1;
    }
    asm volatile("barrier.cluster.arrive.aligned;" ::: "memory");
    asm volatile("barrier.cluster.wait.aligned;"   ::: "memory");
}

// ------------- prefix gram S[b][i][t]=dot/max(i,1), 64x64 tiles, f32x2 -------------
__global__ __launch_bounds__(256) void k_gram(){
    int ti=blockIdx.x, tj=blockIdx.y, b=blockIdx.z;
    if (tj>ti) return;
    __shared__ __align__(16) float As[16][68], Bs[16][68];
    const float* O = g_out1 + (size_t)b*Tt*256;
    int i0=ti*64, t0=tj*64, tid=threadIdx.x;
    int ty=tid>>4, tx=tid&15;
    unsigned long long acc[4][2]={};
    for (int kc=0;kc<256;kc+=16){
        #pragma unroll
        for (int p=0;p<4;p++){
            int e=tid+p*256; int rr=e>>4, kk=e&15;
            As[kk][rr]=O[(i0+rr)*256+kc+kk];
            Bs[kk][rr]=O[(t0+rr)*256+kc+kk];
        }
        __syncthreads();
        #pragma unroll
        for (int kk=0;kk<16;kk++){
            float4 av=*(const float4*)&As[kk][ty*4];
            float4 bv=*(const float4*)&Bs[kk][tx*4];
            unsigned long long b01,b23,ad;
            asm("mov.b64 %0,{%1,%2};":"=l"(b01):"f"(bv.x),"f"(bv.y));
            asm("mov.b64 %0,{%1,%2};":"=l"(b23):"f"(bv.z),"f"(bv.w));
            float avq[4]={av.x,av.y,av.z,av.w};
            #pragma unroll
            for (int q=0;q<4;q++){
                asm("mov.b64 %0,{%1,%1};":"=l"(ad):"f"(avq[q]));
                fma2(acc[q][0], ad, b01);
                fma2(acc[q][1], ad, b23);
            }
        }
        __syncthreads();
    }
    #pragma unroll
    for (int q=0;q<4;q++){
        int i=i0+ty*4+q;
        float sc=1.f/(float)(i>0?i:1);
        float r0,r1,r2,r3;
        asm("mov.b64 {%0,%1},%2;":"=f"(r0),"=f"(r1):"l"(acc[q][0]));
        asm("mov.b64 {%0,%1},%2;":"=f"(r2),"=f"(r3):"l"(acc[q][1]));
        float4 res; res.x=r0*sc; res.y=r1*sc; res.z=r2*sc; res.w=r3*sc;
        *(float4*)&g_S[((size_t)b*Tt+i)*Tt+t0+tx*4] = res;
    }
}

// ------------- softmax over batch per (i,t), t<i -------------
__global__ void k_bsoft(){
    int i=blockIdx.x, t=threadIdx.x;
    if (t>=i) return;
    size_t base=(size_t)i*Tt+t;
    float v[64], m=-1e30f;
    #pragma unroll
    for (int b=0;b<64;b++){ v[b]=g_S[(size_t)b*Tt*Tt+base]; m=fmaxf(m,v[b]); }
    float s=0.f;
    #pragma unroll
    for (int b=0;b<64;b++){ v[b]=__expf(v[b]-m); s+=v[b]; }
    float inv=__fdividef(1.f,s);
    #pragma unroll
    for (int b=0;b<64;b++) g_S[(size_t)b*Tt*Tt+base]=v[b]*inv;
}

// ------------- att[b][i][:] = sum_{t<i} W[b,i,t]*out1[b,t,:], 64x64, f32x2 -------------
__global__ __launch_bounds__(256) void k_apply(){
    int i0=blockIdx.x*64, d0=blockIdx.y*64, b=blockIdx.z;
    __shared__ __align__(16) float Ws[16][68], Os[16][68];
    const float* O=g_out1+(size_t)b*Tt*256;
    const float* W=g_S+(size_t)b*Tt*Tt;
    int tid=threadIdx.x, ty=tid>>4, tx=tid&15;
    unsigned long long acc[4][2]={};
    int kmax=i0+64;
    for (int tk=0;tk<kmax;tk+=16){
        #pragma unroll
        for (int p=0;p<4;p++){
            int e=tid+p*256; int rr=e>>4, kk=e&15;
            int tg=tk+kk;
            Ws[kk][rr] = (tg < i0+rr) ? W[(size_t)(i0+rr)*Tt+tg] : 0.f;
        }
        #pragma unroll
        for (int p=0;p<4;p++){
            int e=tid+p*256; int kk=e>>6, cc=e&63;
            Os[kk][cc]=O[(tk+kk)*256+d0+cc];
        }
        __syncthreads();
        #pragma unroll
        for (int kk=0;kk<16;kk++){
            float4 wv=*(const float4*)&Ws[kk][ty*4];
            float4 ov=*(const float4*)&Os[kk][tx*4];
            unsigned long long o01,o23,wd;
            asm("mov.b64 %0,{%1,%2};":"=l"(o01):"f"(ov.x),"f"(ov.y));
            asm("mov.b64 %0,{%1,%2};":"=l"(o23):"f"(ov.z),"f"(ov.w));
            float wq[4]={wv.x,wv.y,wv.z,wv.w};
            #pragma unroll
            for (int q=0;q<4;q++){
                asm("mov.b64 %0,{%1,%1};":"=l"(wd):"f"(wq[q]));
                fma2(acc[q][0], wd, o01);
                fma2(acc[q][1], wd, o23);
            }
        }
        __syncthreads();
    }
    float* A=g_att+(size_t)b*Tt*256;
    #pragma unroll
    for (int q=0;q<4;q++){
        int i=i0+ty*4+q;
        float r0,r1,r2,r3;
        asm("mov.b64 {%0,%1},%2;":"=f"(r0),"=f"(r1):"l"(acc[q][0]));
        asm("mov.b64 {%0,%1},%2;":"=f"(r2),"=f"(r3):"l"(acc[q][1]));
        float4 res; res.x=r0; res.y=r1; res.z=r2; res.w=r3;
        *(float4*)&A[(size_t)i*256+d0+tx*4] = res;
    }
}

// ------------- full attention: scores + softmax over batch (per t) -------------
__global__ void k_score(int layer){
    const float* O = layer? g_out2 : g_out1;
    const float* h = g_h[layer];
    int t=blockIdx.x, tid=threadIdx.x, w=tid>>5, lane=tid&31;
    __shared__ float sc[64];
    for (int j=0;j<8;j++){
        int b=w*8+j;
        const float* o=O+((size_t)b*Tt+t)*256;
        const float* hb=h+b*256;
        float a=0.f;
        for (int k=lane;k<256;k+=32) a=fmaf(o[k],hb[k],a);
        a=wsum(a);
        if (lane==0) sc[b]=a*(1.f/512.f);
    }
    __syncthreads();
    if (tid<32){
        float v0=sc[tid], v1=sc[tid+32];
        float m=fmaxf(v0,v1);
        #pragma unroll
        for (int o=16;o;o>>=1) m=fmaxf(m,__shfl_xor_sync(0xffffffffu,m,o));
        float e0=__expf(v0-m), e1=__expf(v1-m);
        float s=e0+e1;
        s=wsum(s);
        float inv=__fdividef(1.f,s);
        g_sc[t*64+tid]=e0*inv;
        g_sc[t*64+tid+32]=e1*inv;
    }
}

__global__ void k_fsum1(int layer){
    const float* O = layer? g_out2 : g_out1;
    int b=blockIdx.x, tc=blockIdx.y, d=threadIdx.x;
    const float* o=O+(size_t)b*Tt*256;
    float a=0.f;
    int t0=tc*64;
    for (int t=t0;t<t0+64;t++) a=fmaf(g_sc[t*64+b], o[t*256+d], a);
    g_part[b][tc][d]=a;
}
__global__ void k_fsum2(int layer){
    int b=blockIdx.x, d=threadIdx.x;
    float a=0.f;
    #pragma unroll
    for (int c=0;c<8;c++) a+=g_part[b][c][d];
    if (layer==0) g_att[((size_t)b*Tt+511)*256+d]=a;
    else          g_a2[b*256+d]=a;
}

// ------------- layer-2 input projection GEMM: xg2 = att @ Wih2^T + bias, f32x2 -------------
__global__ __launch_bounds__(256) void k_xg2(
    const float* __restrict__ Wf, const float* __restrict__ bf1, const float* __restrict__ bf2,
    const float* __restrict__ Wb, const float* __restrict__ bb1, const float* __restrict__ bb2)
{
    int t0=blockIdx.x*64, col0=blockIdx.y*64;
    int z=blockIdx.z; int b=z>>1, dir=z&1;
    const float* W2 = dir? Wb : Wf;
    __shared__ __align__(16) float As[16][68], Bs[16][68];
    __shared__ float bsh[64];
    int tid=threadIdx.x, ty=tid>>4, tx=tid&15;
    if (tid<64) bsh[tid] = dir? (bb1[col0+tid]+bb2[col0+tid]) : (bf1[col0+tid]+bf2[col0+tid]);
    const float* A = g_att + (size_t)b*Tt*256;
    unsigned long long acc[4][2]={};
    for (int kc=0;kc<256;kc+=16){
        #pragma unroll
        for (int pq=0;pq<4;pq++){
            int e=tid+pq*256; int rr=e>>4, kk=e&15;
            As[kk][rr]=A[(t0+rr)*256+kc+kk];
            Bs[kk][rr]=W2[(col0+rr)*256+kc+kk];
        }
        __syncthreads();
        #pragma unroll
        for (int kk=0;kk<16;kk++){
            float4 av=*(const float4*)&As[kk][ty*4];
            float4 bv=*(const float4*)&Bs[kk][tx*4];
            unsigned long long b01,b23,ad;
            asm("mov.b64 %0,{%1,%2};":"=l"(b01):"f"(bv.x),"f"(bv.y));
            asm("mov.b64 %0,{%1,%2};":"=l"(b23):"f"(bv.z),"f"(bv.w));
            float avq[4]={av.x,av.y,av.z,av.w};
            #pragma unroll
            for (int q=0;q<4;q++){
                asm("mov.b64 %0,{%1,%1};":"=l"(ad):"f"(avq[q]));
                fma2(acc[q][0], ad, b01);
                fma2(acc[q][1], ad, b23);
            }
        }
        __syncthreads();
    }
    #pragma unroll
    for (int q=0;q<4;q++){
        int t=t0+ty*4+q;
        float r0,r1,r2,r3;
        asm("mov.b64 {%0,%1},%2;":"=f"(r0),"=f"(r1):"l"(acc[q][0]));
        asm("mov.b64 {%0,%1},%2;":"=f"(r2),"=f"(r3):"l"(acc[q][1]));
        float4 res;
        res.x=r0+bsh[tx*4+0]; res.y=r1+bsh[tx*4+1];
        res.z=r2+bsh[tx*4+2]; res.w=r3+bsh[tx*4+3];
        *(float4*)&g_xg[dir][(t*Bb+b)*512 + col0 + tx*4] = res;
    }
}

__global__ void k_final(const float* __restrict__ W, const float* __restrict__ bb, float* out){
    __shared__ float w[256];
    int tid=threadIdx.x;
    for (int i=tid;i<256;i+=64) w[i]=W[i];
    __syncthreads();
    float a=bb[0];
    for (int k=0;k<256;k++) a=fmaf(g_a2[tid*256+k],w[k],a);
    out[tid]=sigm_fast(a);
}

extern "C" void kernel_launch(void* const* d_in, const int* in_sizes, int n_in,
                              void* d_out, int out_size)
{
    const int*   x   = (const int*)  d_in[0];
    const float* emb = (const float*)d_in[1];
    const float* l1Wihf=(const float*)d_in[2],  *l1Whhf=(const float*)d_in[3];
    const float* l1bihf=(const float*)d_in[4],  *l1bhhf=(const float*)d_in[5];
    const float* l1Wihb=(const float*)d_in[6],  *l1Whhb=(const float*)d_in[7];
    const float* l1bihb=(const float*)d_in[8],  *l1bhhb=(const float*)d_in[9];
    const float* l2Wihf=(const float*)d_in[10], *l2Whhf=(const float*)d_in[11];
    const float* l2bihf=(const float*)d_in[12], *l2bhhf=(const float*)d_in[13];
    const float* l2Wihb=(const float*)d_in[14], *l2Whhb=(const float*)d_in[15];
    const float* l2bihb=(const float*)d_in[16], *l2bhhb=(const float*)d_in[17];
    const float* linW=(const float*)d_in[18],   *linb=(const float*)d_in[19];
    float* out=(float*)d_out;

    k_xg1<<<dim3(8,64),256>>>(x,emb,l1Wihf,l1bihf,l1bhhf,l1Wihb,l1bihb,l1bhhb);
    k_rec<<<128,256>>>(0,l1Whhf,l1Whhb);
    k_gram<<<dim3(8,8,64),256>>>();
    k_bsoft<<<512,512>>>();
    k_apply<<<dim3(8,4,64),256>>>();
    k_score<<<512,256>>>(0);
    k_fsum1<<<dim3(64,8),256>>>(0);
    k_fsum2<<<64,256>>>(0);
    k_xg2<<<dim3(8,8,128),256>>>(l2Wihf,l2bihf,l2bhhf,l2Wihb,l2bihb,l2bhhb);
    k_rec<<<128,256>>>(1,l2Whhf,l2Whhb);
    k_score<<<512,256>>>(1);
    k_fsum1<<<dim3(64,8),256>>>(1);
    k_fsum2<<<64,256>>>(1);
    k_final<<<1,64>>>(linW,linb,out);
}

// round 11
// speedup vs baseline: 3.2050x; 1.2917x over previous
#include <cuda_runtime.h>
#include <stdint.h>
#include <math.h>

#define Tt 512
#define Bb 64

// ------------- static device scratch -------------
__device__ float g_xg[2][Tt*Bb*512];      // [dir][(t*64+b)*512+col]
__device__ float g_out1[Bb*Tt*256];
__device__ float g_out2[Bb*Tt*256];
__device__ float g_att[Bb*Tt*256];
__device__ float g_S[(size_t)Bb*Tt*Tt];   // gram -> softmaxed weights in place
__device__ float g_h[2][2*Bb*128];
__device__ float g_sc[Tt*Bb];
__device__ float g_a2[Bb*256];
__device__ float g_part[Bb][8][256];

__device__ __forceinline__ float sigm_fast(float x){ return __fdividef(1.f, 1.f + __expf(-x)); }
__device__ __forceinline__ float tanh_fast(float x){ return 1.f - __fdividef(2.f, __expf(2.f*x) + 1.f); }
__device__ __forceinline__ float wsum(float v){
    #pragma unroll
    for (int o=16;o;o>>=1) v += __shfl_xor_sync(0xffffffffu, v, o);
    return v;
}
__device__ __forceinline__ void fma2(unsigned long long &acc, unsigned long long a, unsigned long long b){
    asm("fma.rn.f32x2 %0, %1, %2, %0;" : "+l"(acc) : "l"(a), "l"(b));
}
__device__ __forceinline__ unsigned int tf32cvt(float x){
    unsigned int u; asm("cvt.rna.tf32.f32 %0, %1;" : "=r"(u) : "f"(x)); return u;
}
__device__ __forceinline__ void mma8(float* c, unsigned int a0,unsigned int a1,unsigned int a2,unsigned int a3,
                                     unsigned int b0,unsigned int b1){
    asm volatile("mma.sync.aligned.m16n8k8.row.col.f32.tf32.tf32.f32 "
        "{%0,%1,%2,%3}, {%4,%5,%6,%7}, {%8,%9}, {%0,%1,%2,%3};"
        : "+f"(c[0]),"+f"(c[1]),"+f"(c[2]),"+f"(c[3])
        : "r"(a0),"r"(a1),"r"(a2),"r"(a3),"r"(b0),"r"(b1));
}

// ------------- layer-1 input projection (embedding fused), both dirs -------------
__global__ __launch_bounds__(256) void k_xg1(
    const int* __restrict__ x, const float* __restrict__ emb,
    const float* __restrict__ Wf, const float* __restrict__ bf1, const float* __restrict__ bf2,
    const float* __restrict__ Wb, const float* __restrict__ bb1, const float* __restrict__ bb2)
{
    __shared__ float wf[5120], wb[5120], bf[512], bb[512], e[10];
    int b = blockIdx.y, t0 = blockIdx.x*64, tid = threadIdx.x;
    for (int i=tid;i<5120;i+=256){ wf[i]=Wf[i]; wb[i]=Wb[i]; }
    for (int i=tid;i<512;i+=256){ bf[i]=bf1[i]+bf2[i]; bb[i]=bb1[i]+bb2[i]; }
    __syncthreads();
    for (int tl=0; tl<64; tl++){
        int t = t0+tl;
        if (tid<10) e[tid] = emb[x[b*Tt+t]*10+tid];
        __syncthreads();
        float ev[10];
        #pragma unroll
        for (int d=0;d<10;d++) ev[d]=e[d];
        for (int c=tid;c<512;c+=256){
            float af=bf[c], ab=bb[c];
            #pragma unroll
            for (int d=0;d<10;d++){ af=fmaf(ev[d],wf[c*10+d],af); ab=fmaf(ev[d],wb[c*10+d],ab); }
            g_xg[0][(t*Bb+b)*512+c]=af;
            g_xg[1][(t*Bb+b)*512+c]=ab;
        }
        __syncthreads();
    }
}

// ------------- persistent bidirectional LSTM recurrence, cluster-of-2 -------------
// mbarrier count=256: 128 peer arrivals (cluster) + 128 local arrivals (cta release
// over local hsh writes) -> acquire-wait alone synchronizes; no post-wait syncthreads.
__global__ __launch_bounds__(256,1) __cluster_dims__(2,1,1)
void k_rec(int layer, const float* __restrict__ Whh_f, const float* __restrict__ Whh_b)
{
    __shared__ __align__(16) float hsh[2][2][128];   // [phase][batch][j]
    __shared__ float gsh[2][256];                    // [batch][g*64+kl]
    __shared__ __align__(8) unsigned long long mbar[2];
    int cid = blockIdx.x>>1;
    unsigned int rank; asm("mov.u32 %0, %%cluster_ctarank;" : "=r"(rank));
    int dir = cid>>5, bpair = cid&31;
    int kb = (int)rank*64;
    int b0 = bpair*2;
    const float* Whh = dir? Whh_b : Whh_f;
    const float* xg  = g_xg[dir];
    float* out = layer? g_out2 : g_out1;
    int tid = threadIdx.x;
    int g = tid>>6, kl = tid&63;
    int grow = g*128 + kb + kl;

    unsigned long long wp[64];
    {
        const float4* wr = (const float4*)&Whh[grow*128];
        #pragma unroll
        for (int i=0;i<32;i++){
            float4 w = __ldg(&wr[i]);
            asm("mov.b64 %0, {%1,%2};" : "=l"(wp[2*i])   : "f"(w.x), "f"(w.y));
            asm("mov.b64 %0, {%1,%2};" : "=l"(wp[2*i+1]) : "f"(w.z), "f"(w.w));
        }
    }
    for (int i=tid;i<512;i+=256) ((float*)hsh)[i]=0.f;

    int cbl = tid>>6, ckl = tid&63;
    float cst = 0.f;

    unsigned int hbase;
    asm("{ .reg .u64 t; cvta.to.shared.u64 t, %1; cvt.u32.u64 %0, t; }" : "=r"(hbase) : "l"((void*)hsh));
    unsigned int mbase;
    asm("{ .reg .u64 t; cvta.to.shared.u64 t, %1; cvt.u32.u64 %0, t; }" : "=r"(mbase) : "l"((void*)mbar));
    if (tid==0){
        asm volatile("mbarrier.init.shared.b64 [%0], %1;" :: "r"(mbase),   "r"(256u) : "memory");
        asm volatile("mbarrier.init.shared.b64 [%0], %1;" :: "r"(mbase+8), "r"(256u) : "memory");
    }
    unsigned int peer_hbase, peer_mbase;
    asm("mapa.shared::cluster.u32 %0, %1, %2;" : "=r"(peer_hbase) : "r"(hbase), "r"(rank^1u));
    asm("mapa.shared::cluster.u32 %0, %1, %2;" : "=r"(peer_mbase) : "r"(mbase), "r"(rank^1u));

    __syncthreads();
    asm volatile("barrier.cluster.arrive.aligned;" ::: "memory");
    asm volatile("barrier.cluster.wait.aligned;"   ::: "memory");

    int tI = dir? 511 : 0;
    float xgc0 = __ldg(&xg[(tI*Bb + b0  )*512 + grow]);
    float xgc1 = __ldg(&xg[(tI*Bb + b0+1)*512 + grow]);
    int p = 0;
    int par0 = 0, par1 = 0;

    for (int s=0; s<Tt; s++){
        int t = dir ? (511-s) : s;
        unsigned long long a0e=0ull, a0o=0ull, a1e=0ull, a1o=0ull;
        const ulonglong2* h0p = (const ulonglong2*)hsh[p][0];
        const ulonglong2* h1p = (const ulonglong2*)hsh[p][1];
        #pragma unroll
        for (int i=0;i<32;i++){
            ulonglong2 ha = h0p[i], hb = h1p[i];
            fma2(a0e, wp[2*i],   ha.x);
            fma2(a0o, wp[2*i+1], ha.y);
            fma2(a1e, wp[2*i],   hb.x);
            fma2(a1o, wp[2*i+1], hb.y);
        }
        float u0,v0,u1,v1,u2,v2,u3,v3;
        asm("mov.b64 {%0,%1}, %2;" : "=f"(u0),"=f"(v0) : "l"(a0e));
        asm("mov.b64 {%0,%1}, %2;" : "=f"(u1),"=f"(v1) : "l"(a0o));
        asm("mov.b64 {%0,%1}, %2;" : "=f"(u2),"=f"(v2) : "l"(a1e));
        asm("mov.b64 {%0,%1}, %2;" : "=f"(u3),"=f"(v3) : "l"(a1o));
        gsh[0][tid] = (u0+v0) + (u1+v1) + xgc0;
        gsh[1][tid] = (u2+v2) + (u3+v3) + xgc1;
        if (s<511){
            int tn = dir? (510-s) : (s+1);
            xgc0 = __ldg(&xg[(tn*Bb + b0  )*512 + grow]);
            xgc1 = __ldg(&xg[(tn*Bb + b0+1)*512 + grow]);
        }
        __syncthreads();
        int np = p^1;
        if (tid<128){
            float gi=gsh[cbl][ckl], gf=gsh[cbl][64+ckl], gg=gsh[cbl][128+ckl], go=gsh[cbl][192+ckl];
            cst = sigm_fast(gf)*cst + sigm_fast(gi)*tanh_fast(gg);
            float hv = sigm_fast(go)*tanh_fast(cst);
            int k = kb + ckl;
            out[((b0+cbl)*Tt + t)*256 + dir*128 + k] = hv;
            if (s==511){
                g_h[layer][dir*Bb*128 + (b0+cbl)*128 + k] = hv;
            } else {
                hsh[np][cbl][k] = hv;
                unsigned int off = (unsigned int)(((np*2+cbl)*128 + k)*4);
                asm volatile("st.shared::cluster.f32 [%0], %1;" :: "r"(peer_hbase+off), "f"(hv) : "memory");
                asm volatile("mbarrier.arrive.shared::cluster.b64 _, [%0];" :: "r"(peer_mbase + (unsigned)np*8u) : "memory");
                asm volatile("mbarrier.arrive.shared.b64 _, [%0];" :: "r"(mbase + (unsigned)np*8u) : "memory");
            }
        }
        if (s<511){
            int ph = np ? par1 : par0;
            unsigned int mbaddr = mbase + (unsigned)np*8u;
            unsigned int done;
            asm volatile(
                "{\n\t.reg .pred p;\n\t"
                "mbarrier.try_wait.parity.acquire.cluster.shared::cta.b64 p, [%1], %2;\n\t"
                "selp.b32 %0, 1, 0, p;\n\t}"
                : "=r"(done) : "r"(mbaddr), "r"((unsigned)ph) : "memory");
            while (!done){
                asm volatile(
                    "{\n\t.reg .pred p;\n\t"
                    "mbarrier.try_wait.parity.acquire.cluster.shared::cta.b64 p, [%1], %2, 0x989680;\n\t"
                    "selp.b32 %0, 1, 0, p;\n\t}"
                    : "=r"(done) : "r"(mbaddr), "r"((unsigned)ph) : "memory");
            }
            if (np) par1^=1; else par0^=1;
        }
        p ^= 1;
    }
    asm volatile("barrier.cluster.arrive.aligned;" ::: "memory");
    asm volatile("barrier.cluster.wait.aligned;"   ::: "memory");
}

// ------------- prefix gram S[b][i][t]=dot/max(i,1), tf32 mma, 64x64 tiles -------------
__global__ __launch_bounds__(256) void k_gram(){
    int ti=blockIdx.x, tj=blockIdx.y, b=blockIdx.z;
    if (tj>ti) return;
    __shared__ unsigned int As[64*36], Bs[64*36];
    const float* O = g_out1 + (size_t)b*Tt*256;
    int i0=ti*64, t0=tj*64, tid=threadIdx.x;
    int lane=tid&31, wid=tid>>5, g=lane>>2, tg=lane&3;
    int wm=wid>>1, wn=wid&1;
    float acc[4][4]={};
    for (int kc=0;kc<256;kc+=32){
        #pragma unroll
        for (int e=0;e<2;e++){
            int idx=tid+e*256; int m=idx>>3, k4=idx&7;
            float4 va=*(const float4*)&O[(i0+m)*256+kc+k4*4];
            float4 vb=*(const float4*)&O[(t0+m)*256+kc+k4*4];
            int base=m*36+k4*4;
            As[base]=tf32cvt(va.x); As[base+1]=tf32cvt(va.y); As[base+2]=tf32cvt(va.z); As[base+3]=tf32cvt(va.w);
            Bs[base]=tf32cvt(vb.x); Bs[base+1]=tf32cvt(vb.y); Bs[base+2]=tf32cvt(vb.z); Bs[base+3]=tf32cvt(vb.w);
        }
        __syncthreads();
        #pragma unroll
        for (int ks=0;ks<4;ks++){
            int ko=ks*8;
            unsigned int a0=As[(wm*16+g)*36+ko+tg],   a1=As[(wm*16+g+8)*36+ko+tg];
            unsigned int a2=As[(wm*16+g)*36+ko+tg+4], a3=As[(wm*16+g+8)*36+ko+tg+4];
            #pragma unroll
            for (int nt=0;nt<4;nt++){
                int no=wn*32+nt*8;
                unsigned int b0=Bs[(no+g)*36+ko+tg], b1=Bs[(no+g)*36+ko+tg+4];
                mma8(acc[nt], a0,a1,a2,a3,b0,b1);
            }
        }
        __syncthreads();
    }
    int i_a = i0 + wm*16 + g, i_b = i_a + 8;
    float sa = 1.f/(float)(i_a>0?i_a:1), sb = 1.f/(float)(i_b>0?i_b:1);
    #pragma unroll
    for (int nt=0;nt<4;nt++){
        int col = t0 + wn*32 + nt*8 + tg*2;
        float2 r0; r0.x=acc[nt][0]*sa; r0.y=acc[nt][1]*sa;
        float2 r1; r1.x=acc[nt][2]*sb; r1.y=acc[nt][3]*sb;
        *(float2*)&g_S[((size_t)b*Tt+i_a)*Tt+col]=r0;
        *(float2*)&g_S[((size_t)b*Tt+i_b)*Tt+col]=r1;
    }
}

// ------------- softmax over batch per (i,t), t<i -------------
__global__ void k_bsoft(){
    int i=blockIdx.x, t=threadIdx.x;
    if (t>=i) return;
    size_t base=(size_t)i*Tt+t;
    float v[64], m=-1e30f;
    #pragma unroll
    for (int b=0;b<64;b++){ v[b]=g_S[(size_t)b*Tt*Tt+base]; m=fmaxf(m,v[b]); }
    float s=0.f;
    #pragma unroll
    for (int b=0;b<64;b++){ v[b]=__expf(v[b]-m); s+=v[b]; }
    float inv=__fdividef(1.f,s);
    #pragma unroll
    for (int b=0;b<64;b++) g_S[(size_t)b*Tt*Tt+base]=v[b]*inv;
}

// ------------- att[b][i][:] = sum_{t<i} W[b,i,t]*out1[b,t,:], tf32 mma -------------
__global__ __launch_bounds__(256) void k_apply(){
    int i0=blockIdx.x*64, d0=blockIdx.y*64, b=blockIdx.z;
    __shared__ unsigned int As[64*36], Bs[64*36];
    const float* O=g_out1+(size_t)b*Tt*256;
    const float* W=g_S+(size_t)b*Tt*Tt;
    int tid=threadIdx.x;
    int lane=tid&31, wid=tid>>5, g=lane>>2, tg=lane&3;
    int wm=wid>>1, wn=wid&1;
    float acc[4][4]={};
    int kmax=i0+64;
    for (int tk=0;tk<kmax;tk+=32){
        #pragma unroll
        for (int e=0;e<2;e++){
            int idx=tid+e*256; int m=idx>>3, k4=idx&7;
            int i_r = i0+m;
            int tbase = tk+k4*4;
            float4 va=*(const float4*)&W[(size_t)i_r*Tt + tbase];
            if (tbase+0 >= i_r) va.x=0.f;
            if (tbase+1 >= i_r) va.y=0.f;
            if (tbase+2 >= i_r) va.z=0.f;
            if (tbase+3 >= i_r) va.w=0.f;
            int base=m*36+k4*4;
            As[base]=tf32cvt(va.x); As[base+1]=tf32cvt(va.y); As[base+2]=tf32cvt(va.z); As[base+3]=tf32cvt(va.w);
        }
        #pragma unroll
        for (int e=0;e<2;e++){
            int idx=tid+e*256; int k=idx&31, n4=idx>>5;
            float4 v=*(const float4*)&O[(tk+k)*256 + d0+n4*4];
            Bs[(n4*4  )*36+k]=tf32cvt(v.x);
            Bs[(n4*4+1)*36+k]=tf32cvt(v.y);
            Bs[(n4*4+2)*36+k]=tf32cvt(v.z);
            Bs[(n4*4+3)*36+k]=tf32cvt(v.w);
        }
        __syncthreads();
        #pragma unroll
        for (int ks=0;ks<4;ks++){
            int ko=ks*8;
            unsigned int a0=As[(wm*16+g)*36+ko+tg],   a1=As[(wm*16+g+8)*36+ko+tg];
            unsigned int a2=As[(wm*16+g)*36+ko+tg+4], a3=As[(wm*16+g+8)*36+ko+tg+4];
            #pragma unroll
            for (int nt=0;nt<4;nt++){
                int no=wn*32+nt*8;
                unsigned int b0=Bs[(no+g)*36+ko+tg], b1=Bs[(no+g)*36+ko+tg+4];
                mma8(acc[nt], a0,a1,a2,a3,b0,b1);
            }
        }
        __syncthreads();
    }
    float* A=g_att+(size_t)b*Tt*256;
    int i_a = i0 + wm*16 + g, i_b = i_a + 8;
    #pragma unroll
    for (int nt=0;nt<4;nt++){
        int col = d0 + wn*32 + nt*8 + tg*2;
        float2 r0; r0.x=acc[nt][0]; r0.y=acc[nt][1];
        float2 r1; r1.x=acc[nt][2]; r1.y=acc[nt][3];
        *(float2*)&A[(size_t)i_a*256+col]=r0;
        *(float2*)&A[(size_t)i_b*256+col]=r1;
    }
}

// ------------- full attention: scores + softmax over batch (per t) -------------
__global__ void k_score(int layer){
    const float* O = layer? g_out2 : g_out1;
    const float* h = g_h[layer];
    int t=blockIdx.x, tid=threadIdx.x, w=tid>>5, lane=tid&31;
    __shared__ float sc[64];
    for (int j=0;j<8;j++){
        int b=w*8+j;
        const float* o=O+((size_t)b*Tt+t)*256;
        const float* hb=h+b*256;
        float a=0.f;
        for (int k=lane;k<256;k+=32) a=fmaf(o[k],hb[k],a);
        a=wsum(a);
        if (lane==0) sc[b]=a*(1.f/512.f);
    }
    __syncthreads();
    if (tid<32){
        float v0=sc[tid], v1=sc[tid+32];
        float m=fmaxf(v0,v1);
        #pragma unroll
        for (int o=16;o;o>>=1) m=fmaxf(m,__shfl_xor_sync(0xffffffffu,m,o));
        float e0=__expf(v0-m), e1=__expf(v1-m);
        float s=e0+e1;
        s=wsum(s);
        float inv=__fdividef(1.f,s);
        g_sc[t*64+tid]=e0*inv;
        g_sc[t*64+tid+32]=e1*inv;
    }
}

__global__ void k_fsum1(int layer){
    const float* O = layer? g_out2 : g_out1;
    int b=blockIdx.x, tc=blockIdx.y, d=threadIdx.x;
    const float* o=O+(size_t)b*Tt*256;
    float a=0.f;
    int t0=tc*64;
    for (int t=t0;t<t0+64;t++) a=fmaf(g_sc[t*64+b], o[t*256+d], a);
    g_part[b][tc][d]=a;
}
__global__ void k_fsum2(int layer){
    int b=blockIdx.x, d=threadIdx.x;
    float a=0.f;
    #pragma unroll
    for (int c=0;c<8;c++) a+=g_part[b][c][d];
    if (layer==0) g_att[((size_t)b*Tt+511)*256+d]=a;
    else          g_a2[b*256+d]=a;
}

// ------------- layer-2 input projection GEMM: xg2 = att @ Wih2^T + bias, tf32 mma -------------
__global__ __launch_bounds__(256) void k_xg2(
    const float* __restrict__ Wf, const float* __restrict__ bf1, const float* __restrict__ bf2,
    const float* __restrict__ Wb, const float* __restrict__ bb1, const float* __restrict__ bb2)
{
    int t0=blockIdx.x*64, col0=blockIdx.y*64;
    int z=blockIdx.z; int b=z>>1, dir=z&1;
    const float* W2 = dir? Wb : Wf;
    __shared__ unsigned int As[64*36], Bs[64*36];
    __shared__ float bsh[64];
    int tid=threadIdx.x;
    int lane=tid&31, wid=tid>>5, g=lane>>2, tg=lane&3;
    int wm=wid>>1, wn=wid&1;
    if (tid<64) bsh[tid] = dir? (bb1[col0+tid]+bb2[col0+tid]) : (bf1[col0+tid]+bf2[col0+tid]);
    const float* A = g_att + (size_t)b*Tt*256;
    float acc[4][4]={};
    for (int kc=0;kc<256;kc+=32){
        #pragma unroll
        for (int e=0;e<2;e++){
            int idx=tid+e*256; int m=idx>>3, k4=idx&7;
            float4 va=*(const float4*)&A[(t0+m)*256+kc+k4*4];
            float4 vb=*(const float4*)&W2[(col0+m)*256+kc+k4*4];
            int base=m*36+k4*4;
            As[base]=tf32cvt(va.x); As[base+1]=tf32cvt(va.y); As[base+2]=tf32cvt(va.z); As[base+3]=tf32cvt(va.w);
            Bs[base]=tf32cvt(vb.x); Bs[base+1]=tf32cvt(vb.y); Bs[base+2]=tf32cvt(vb.z); Bs[base+3]=tf32cvt(vb.w);
        }
        __syncthreads();
        #pragma unroll
        for (int ks=0;ks<4;ks++){
            int ko=ks*8;
            unsigned int a0=As[(wm*16+g)*36+ko+tg],   a1=As[(wm*16+g+8)*36+ko+tg];
            unsigned int a2=As[(wm*16+g)*36+ko+tg+4], a3=As[(wm*16+g+8)*36+ko+tg+4];
            #pragma unroll
            for (int nt=0;nt<4;nt++){
                int no=wn*32+nt*8;
                unsigned int b0=Bs[(no+g)*36+ko+tg], b1=Bs[(no+g)*36+ko+tg+4];
                mma8(acc[nt], a0,a1,a2,a3,b0,b1);
            }
        }
        __syncthreads();
    }
    int t_a = t0 + wm*16 + g, t_b = t_a + 8;
    #pragma unroll
    for (int nt=0;nt<4;nt++){
        int cl = wn*32 + nt*8 + tg*2;
        float2 r0; r0.x=acc[nt][0]+bsh[cl]; r0.y=acc[nt][1]+bsh[cl+1];
        float2 r1; r1.x=acc[nt][2]+bsh[cl]; r1.y=acc[nt][3]+bsh[cl+1];
        *(float2*)&g_xg[dir][(t_a*Bb+b)*512 + col0 + cl] = r0;
        *(float2*)&g_xg[dir][(t_b*Bb+b)*512 + col0 + cl] = r1;
    }
}

__global__ void k_final(const float* __restrict__ W, const float* __restrict__ bb, float* out){
    __shared__ float w[256];
    int tid=threadIdx.x;
    for (int i=tid;i<256;i+=64) w[i]=W[i];
    __syncthreads();
    float a=bb[0];
    for (int k=0;k<256;k++) a=fmaf(g_a2[tid*256+k],w[k],a);
    out[tid]=sigm_fast(a);
}

extern "C" void kernel_launch(void* const* d_in, const int* in_sizes, int n_in,
                              void* d_out, int out_size)
{
    const int*   x   = (const int*)  d_in[0];
    const float* emb = (const float*)d_in[1];
    const float* l1Wihf=(const float*)d_in[2],  *l1Whhf=(const float*)d_in[3];
    const float* l1bihf=(const float*)d_in[4],  *l1bhhf=(const float*)d_in[5];
    const float* l1Wihb=(const float*)d_in[6],  *l1Whhb=(const float*)d_in[7];
    const float* l1bihb=(const float*)d_in[8],  *l1bhhb=(const float*)d_in[9];
    const float* l2Wihf=(const float*)d_in[10], *l2Whhf=(const float*)d_in[11];
    const float* l2bihf=(const float*)d_in[12], *l2bhhf=(const float*)d_in[13];
    const float* l2Wihb=(const float*)d_in[14], *l2Whhb=(const float*)d_in[15];
    const float* l2bihb=(const float*)d_in[16], *l2bhhb=(const float*)d_in[17];
    const float* linW=(const float*)d_in[18],   *linb=(const float*)d_in[19];
    float* out=(float*)d_out;

    k_xg1<<<dim3(8,64),256>>>(x,emb,l1Wihf,l1bihf,l1bhhf,l1Wihb,l1bihb,l1bhhb);
    k_rec<<<128,256>>>(0,l1Whhf,l1Whhb);
    k_gram<<<dim3(8,8,64),256>>>();
    k_bsoft<<<512,512>>>();
    k_apply<<<dim3(8,4,64),256>>>();
    k_score<<<512,256>>>(0);
    k_fsum1<<<dim3(64,8),256>>>(0);
    k_fsum2<<<64,256>>>(0);
    k_xg2<<<dim3(8,8,128),256>>>(l2Wihf,l2bihf,l2bhhf,l2Wihb,l2bihb,l2bhhb);
    k_rec<<<128,256>>>(1,l2Whhf,l2Whhb);
    k_score<<<512,256>>>(1);
    k_fsum1<<<dim3(64,8),256>>>(1);
    k_fsum2<<<64,256>>>(1);
    k_final<<<1,64>>>(linW,linb,out);
}